// round 13
// baseline (speedup 1.0000x reference)
#include <cuda_runtime.h>
#include <cuda_bf16.h>
#include <math.h>
#include <stdint.h>

#define NMAX 50000
#define EMAX 200000
#define ETMAX (NMAX + EMAX)

// ---------------- scratch (device globals; no allocations allowed) ----------
__device__ float g_h1[(size_t)NMAX * 1024];   // GEMM outputs (h), reused per layer
__device__ float g_es[(size_t)NMAX * 8];
__device__ float g_ed[(size_t)NMAX * 8];
__device__ float g_w [(size_t)ETMAX * 8];
__device__ int   g_src[ETMAX];
__device__ int   g_dst[ETMAX];
__device__ int   g_is64;
// CSR by dst
__device__ int   g_cnt[NMAX];
__device__ int   g_roff[NMAX + 1];
__device__ int   g_pos[NMAX];
__device__ int   g_bsum[64];
__device__ int   g_eid[ETMAX];
// pre-split A operand (hi/lo bf16), [N][Kpad]
__device__ __nv_bfloat16 g_ah[(size_t)NMAX * 1024];
__device__ __nv_bfloat16 g_al[(size_t)NMAX * 1024];
// transposed + hi/lo-split weights, [Nc][Kpad] bf16
__device__ __nv_bfloat16 g_wth[131072];
__device__ __nv_bfloat16 g_wtl[131072];

// ================= edge preprocessing =======================================
__global__ void detect_dtype(const void* ei, int N) {
    if (blockIdx.x == 0 && threadIdx.x == 0) {
        const long long* p = (const long long*)ei;
        int ok = 1;
        for (int i = 0; i < 64; i++) {
            long long v = p[i];
            if (v < 0 || v >= (long long)N) { ok = 0; break; }
        }
        g_is64 = ok;
    }
}
__global__ void prep_edges(const void* ei, int E, int ET) {
    int i = blockIdx.x * blockDim.x + threadIdx.x;
    if (i >= ET) return;
    int s, d;
    if (i < E) {
        if (g_is64) { const long long* p = (const long long*)ei; s = (int)p[i]; d = (int)p[E + i]; }
        else        { const int* p = (const int*)ei; s = p[i]; d = p[E + i]; }
    } else { s = d = i - E; }
    g_src[i] = s; g_dst[i] = d;
}

// ---------------- CSR build --------------------------------------------------
__global__ void csr_hist(int ET) {
    int i = blockIdx.x * blockDim.x + threadIdx.x;
    if (i < ET) atomicAdd(&g_cnt[g_dst[i]], 1);
}
#define SCAN_B 1024
__global__ void scan1(int n) {
    __shared__ int sh[SCAN_B];
    int gid = blockIdx.x * SCAN_B + threadIdx.x;
    int v = (gid < n) ? g_cnt[gid] : 0;
    sh[threadIdx.x] = v;
    __syncthreads();
    for (int o = 1; o < SCAN_B; o <<= 1) {
        int t = (threadIdx.x >= o) ? sh[threadIdx.x - o] : 0;
        __syncthreads();
        sh[threadIdx.x] += t;
        __syncthreads();
    }
    if (gid < n) g_roff[gid] = sh[threadIdx.x] - v;   // exclusive
    if (threadIdx.x == SCAN_B - 1) g_bsum[blockIdx.x] = sh[threadIdx.x];
}
__global__ void scan2(int nb) {
    __shared__ int sh[64];
    int v = (threadIdx.x < nb) ? g_bsum[threadIdx.x] : 0;
    sh[threadIdx.x] = v;
    __syncthreads();
    for (int o = 1; o < 64; o <<= 1) {
        int t = (threadIdx.x >= o) ? sh[threadIdx.x - o] : 0;
        __syncthreads();
        sh[threadIdx.x] += t;
        __syncthreads();
    }
    if (threadIdx.x < nb) g_bsum[threadIdx.x] = sh[threadIdx.x] - v;
}
__global__ void scan3(int n, int ET) {
    int gid = blockIdx.x * SCAN_B + threadIdx.x;
    if (gid < n) {
        int v = g_roff[gid] + g_bsum[blockIdx.x];
        g_roff[gid] = v;
        g_pos[gid] = v;
    }
    if (gid == 0) g_roff[n] = ET;
}
__global__ void csr_fill(int ET) {
    int i = blockIdx.x * blockDim.x + threadIdx.x;
    if (i >= ET) return;
    int slot = atomicAdd(&g_pos[g_dst[i]], 1);
    g_eid[slot] = i;
}

// ---------------- weight / input prep ---------------------------------------
__global__ void prep_w(const float* __restrict__ W, __nv_bfloat16* __restrict__ hi,
                       __nv_bfloat16* __restrict__ lo, int K, int N, int Kpad) {
    int idx = blockIdx.x * blockDim.x + threadIdx.x;
    if (idx >= N * Kpad) return;
    int n = idx / Kpad, k = idx - n * Kpad;
    float v = (k < K) ? W[(size_t)k * N + n] : 0.f;
    __nv_bfloat16 h = __float2bfloat16(v);
    hi[idx] = h;
    lo[idx] = __float2bfloat16(v - __bfloat162float(h));
}
__global__ void split_x(const float* __restrict__ x, __nv_bfloat16* __restrict__ hi,
                        __nv_bfloat16* __restrict__ lo, int N, int K, int Kpad) {
    int idx = blockIdx.x * blockDim.x + threadIdx.x;
    if (idx >= N * Kpad) return;
    int n = idx / Kpad, k = idx - n * Kpad;
    float v = (k < K) ? x[(size_t)n * K + k] : 0.f;
    __nv_bfloat16 h = __float2bfloat16(v);
    hi[idx] = h;
    lo[idx] = __float2bfloat16(v - __bfloat162float(h));
}

// ================= mma.sync bf16-split GEMMs =================================
#define APAD 72

__device__ __forceinline__ void mma_bf16(float* c, uint32_t a0, uint32_t a1,
                                         uint32_t a2, uint32_t a3,
                                         uint32_t b0, uint32_t b1) {
    asm volatile(
        "mma.sync.aligned.m16n8k16.row.col.f32.bf16.bf16.f32 "
        "{%0,%1,%2,%3}, {%4,%5,%6,%7}, {%8,%9}, {%0,%1,%2,%3};"
        : "+f"(c[0]), "+f"(c[1]), "+f"(c[2]), "+f"(c[3])
        : "r"(a0), "r"(a1), "r"(a2), "r"(a3), "r"(b0), "r"(b1));
}

// ---------- 128x64 tile (R8-proven; used for layer 3) ------------------------
#define SMEM_G64 ((128 * APAD * 2 + 64 * APAD * 2) * 2)   // 55296 bytes

__global__ void __launch_bounds__(256, 2)
gemm_mma64(const __nv_bfloat16* __restrict__ Ah, const __nv_bfloat16* __restrict__ Al,
           const __nv_bfloat16* __restrict__ Bh, const __nv_bfloat16* __restrict__ Bl,
           float* __restrict__ C, int M, int Kpad, int Nc,
           const float* __restrict__ av, const float* __restrict__ adv,
           float* __restrict__ esOut, float* __restrict__ edOut, int H, int Ch) {
    extern __shared__ __nv_bfloat16 sm[];
    __nv_bfloat16* sAh = sm;
    __nv_bfloat16* sAl = sAh + 128 * APAD;
    __nv_bfloat16* sBh = sAl + 128 * APAD;
    __nv_bfloat16* sBl = sBh + 64 * APAD;

    const int tid = threadIdx.x;
    const int rowBase = blockIdx.y * 128, colBase = blockIdx.x * 64;
    const int warp = tid >> 5, lane = tid & 31;
    const int wm = warp & 3, wn = warp >> 2;
    const int g = lane >> 2, t = lane & 3;

    float acc[2][4][4] = {};

    for (int k0 = 0; k0 < Kpad; k0 += 64) {
        #pragma unroll
        for (int i = 0; i < 4; i++) {
            int lin = tid + (i << 8);
            int row = lin >> 3, u = lin & 7;
            int gr = rowBase + row;
            int e = row * APAD + (u << 3);
            uint4 hv = make_uint4(0, 0, 0, 0), lv = make_uint4(0, 0, 0, 0);
            if (gr < M) {
                size_t gidx = (size_t)gr * Kpad + k0 + (u << 3);
                hv = *(const uint4*)(Ah + gidx);
                lv = *(const uint4*)(Al + gidx);
            }
            *(uint4*)(sAh + e) = hv;
            *(uint4*)(sAl + e) = lv;
        }
        #pragma unroll
        for (int i = 0; i < 2; i++) {
            int lin = tid + (i << 8);
            int n = lin >> 3, u = lin & 7;
            size_t gidx = (size_t)(colBase + n) * Kpad + k0 + (u << 3);
            int e = n * APAD + (u << 3);
            *(uint4*)(sBh + e) = *(const uint4*)(Bh + gidx);
            *(uint4*)(sBl + e) = *(const uint4*)(Bl + gidx);
        }
        __syncthreads();

        #pragma unroll
        for (int ks = 0; ks < 4; ks++) {
            const int kc = ks * 16 + t * 2;
            uint32_t ah[2][4], al[2][4];
            #pragma unroll
            for (int ma = 0; ma < 2; ma++) {
                int r0 = wm * 32 + ma * 16 + g;
                ah[ma][0] = *(const uint32_t*)(sAh + r0 * APAD + kc);
                ah[ma][1] = *(const uint32_t*)(sAh + (r0 + 8) * APAD + kc);
                ah[ma][2] = *(const uint32_t*)(sAh + r0 * APAD + kc + 8);
                ah[ma][3] = *(const uint32_t*)(sAh + (r0 + 8) * APAD + kc + 8);
                al[ma][0] = *(const uint32_t*)(sAl + r0 * APAD + kc);
                al[ma][1] = *(const uint32_t*)(sAl + (r0 + 8) * APAD + kc);
                al[ma][2] = *(const uint32_t*)(sAl + r0 * APAD + kc + 8);
                al[ma][3] = *(const uint32_t*)(sAl + (r0 + 8) * APAD + kc + 8);
            }
            #pragma unroll
            for (int na = 0; na < 4; na++) {
                int n0 = wn * 32 + na * 8 + g;
                uint32_t bh0 = *(const uint32_t*)(sBh + n0 * APAD + kc);
                uint32_t bh1 = *(const uint32_t*)(sBh + n0 * APAD + kc + 8);
                uint32_t bl0 = *(const uint32_t*)(sBl + n0 * APAD + kc);
                uint32_t bl1 = *(const uint32_t*)(sBl + n0 * APAD + kc + 8);
                #pragma unroll
                for (int ma = 0; ma < 2; ma++) {
                    mma_bf16(acc[ma][na], ah[ma][0], ah[ma][1], ah[ma][2], ah[ma][3], bh0, bh1);
                    mma_bf16(acc[ma][na], ah[ma][0], ah[ma][1], ah[ma][2], ah[ma][3], bl0, bl1);
                    mma_bf16(acc[ma][na], al[ma][0], al[ma][1], al[ma][2], al[ma][3], bh0, bh1);
                }
            }
        }
        __syncthreads();
    }

    #pragma unroll
    for (int ma = 0; ma < 2; ma++) {
        int row = rowBase + wm * 32 + ma * 16 + g;
        #pragma unroll
        for (int na = 0; na < 4; na++) {
            int col = colBase + wn * 32 + na * 8 + t * 2;
            if (row < M)
                *(float2*)(C + (size_t)row * Nc + col) = make_float2(acc[ma][na][0], acc[ma][na][1]);
            if (row + 8 < M)
                *(float2*)(C + (size_t)(row + 8) * Nc + col) = make_float2(acc[ma][na][2], acc[ma][na][3]);
        }
    }

    {
        const int head = colBase / Ch;
        const int cb = colBase - head * Ch;
        const float* avh = av + head * Ch + cb;
        const float* adh = adv + head * Ch + cb;
        #pragma unroll
        for (int ma = 0; ma < 2; ma++) {
            float pe0 = 0.f, pd0 = 0.f, pe1 = 0.f, pd1 = 0.f;
            #pragma unroll
            for (int na = 0; na < 4; na++) {
                int cl = wn * 32 + na * 8 + t * 2;
                float w0 = avh[cl], w1 = avh[cl + 1];
                float d0 = adh[cl], d1 = adh[cl + 1];
                pe0 += acc[ma][na][0] * w0 + acc[ma][na][1] * w1;
                pd0 += acc[ma][na][0] * d0 + acc[ma][na][1] * d1;
                pe1 += acc[ma][na][2] * w0 + acc[ma][na][3] * w1;
                pd1 += acc[ma][na][2] * d0 + acc[ma][na][3] * d1;
            }
            #pragma unroll
            for (int o = 1; o <= 2; o <<= 1) {
                pe0 += __shfl_xor_sync(0xffffffff, pe0, o);
                pd0 += __shfl_xor_sync(0xffffffff, pd0, o);
                pe1 += __shfl_xor_sync(0xffffffff, pe1, o);
                pd1 += __shfl_xor_sync(0xffffffff, pd1, o);
            }
            if (t == 0) {
                int r = rowBase + wm * 32 + ma * 16 + g;
                if (r < M) {
                    atomicAdd(&esOut[(size_t)r * H + head], pe0);
                    atomicAdd(&edOut[(size_t)r * H + head], pd0);
                }
                if (r + 8 < M) {
                    atomicAdd(&esOut[(size_t)(r + 8) * H + head], pe1);
                    atomicAdd(&edOut[(size_t)(r + 8) * H + head], pd1);
                }
            }
        }
    }
}

// ---------- 128x128 tile (layers 1-2; tile spans exactly one head Ch=128) ----
#define SMEM_G128 ((128 * APAD * 2 + 128 * APAD * 2) * 2)  // 73728 bytes

__global__ void __launch_bounds__(256, 2)
gemm_mma128(const __nv_bfloat16* __restrict__ Ah, const __nv_bfloat16* __restrict__ Al,
            const __nv_bfloat16* __restrict__ Bh, const __nv_bfloat16* __restrict__ Bl,
            float* __restrict__ C, int M, int Kpad, int Nc,
            const float* __restrict__ av, const float* __restrict__ adv,
            float* __restrict__ esOut, float* __restrict__ edOut, int H) {
    extern __shared__ __nv_bfloat16 sm[];
    __nv_bfloat16* sAh = sm;
    __nv_bfloat16* sAl = sAh + 128 * APAD;
    __nv_bfloat16* sBh = sAl + 128 * APAD;
    __nv_bfloat16* sBl = sBh + 128 * APAD;

    const int tid = threadIdx.x;
    const int rowBase = blockIdx.y * 128, colBase = blockIdx.x * 128;
    const int warp = tid >> 5, lane = tid & 31;
    const int wm = warp & 3, wn = warp >> 2;      // 4 (M) x 2 (N) warps; warp tile 32x64
    const int g = lane >> 2, t = lane & 3;

    float acc[2][8][4] = {};

    for (int k0 = 0; k0 < Kpad; k0 += 64) {
        #pragma unroll
        for (int i = 0; i < 4; i++) {
            int lin = tid + (i << 8);
            int row = lin >> 3, u = lin & 7;
            int gr = rowBase + row;
            int e = row * APAD + (u << 3);
            uint4 hv = make_uint4(0, 0, 0, 0), lv = make_uint4(0, 0, 0, 0);
            if (gr < M) {
                size_t gidx = (size_t)gr * Kpad + k0 + (u << 3);
                hv = *(const uint4*)(Ah + gidx);
                lv = *(const uint4*)(Al + gidx);
            }
            *(uint4*)(sAh + e) = hv;
            *(uint4*)(sAl + e) = lv;
        }
        #pragma unroll
        for (int i = 0; i < 4; i++) {
            int lin = tid + (i << 8);
            int n = lin >> 3, u = lin & 7;
            size_t gidx = (size_t)(colBase + n) * Kpad + k0 + (u << 3);
            int e = n * APAD + (u << 3);
            *(uint4*)(sBh + e) = *(const uint4*)(Bh + gidx);
            *(uint4*)(sBl + e) = *(const uint4*)(Bl + gidx);
        }
        __syncthreads();

        #pragma unroll
        for (int ks = 0; ks < 4; ks++) {
            const int kc = ks * 16 + t * 2;
            uint32_t ah[2][4], al[2][4];
            #pragma unroll
            for (int ma = 0; ma < 2; ma++) {
                int r0 = wm * 32 + ma * 16 + g;
                ah[ma][0] = *(const uint32_t*)(sAh + r0 * APAD + kc);
                ah[ma][1] = *(const uint32_t*)(sAh + (r0 + 8) * APAD + kc);
                ah[ma][2] = *(const uint32_t*)(sAh + r0 * APAD + kc + 8);
                ah[ma][3] = *(const uint32_t*)(sAh + (r0 + 8) * APAD + kc + 8);
                al[ma][0] = *(const uint32_t*)(sAl + r0 * APAD + kc);
                al[ma][1] = *(const uint32_t*)(sAl + (r0 + 8) * APAD + kc);
                al[ma][2] = *(const uint32_t*)(sAl + r0 * APAD + kc + 8);
                al[ma][3] = *(const uint32_t*)(sAl + (r0 + 8) * APAD + kc + 8);
            }
            #pragma unroll
            for (int na = 0; na < 8; na++) {
                int n0 = wn * 64 + na * 8 + g;
                uint32_t bh0 = *(const uint32_t*)(sBh + n0 * APAD + kc);
                uint32_t bh1 = *(const uint32_t*)(sBh + n0 * APAD + kc + 8);
                uint32_t bl0 = *(const uint32_t*)(sBl + n0 * APAD + kc);
                uint32_t bl1 = *(const uint32_t*)(sBl + n0 * APAD + kc + 8);
                #pragma unroll
                for (int ma = 0; ma < 2; ma++) {
                    mma_bf16(acc[ma][na], ah[ma][0], ah[ma][1], ah[ma][2], ah[ma][3], bh0, bh1);
                    mma_bf16(acc[ma][na], ah[ma][0], ah[ma][1], ah[ma][2], ah[ma][3], bl0, bl1);
                    mma_bf16(acc[ma][na], al[ma][0], al[ma][1], al[ma][2], al[ma][3], bh0, bh1);
                }
            }
        }
        __syncthreads();
    }

    #pragma unroll
    for (int ma = 0; ma < 2; ma++) {
        int row = rowBase + wm * 32 + ma * 16 + g;
        #pragma unroll
        for (int na = 0; na < 8; na++) {
            int col = colBase + wn * 64 + na * 8 + t * 2;
            if (row < M)
                *(float2*)(C + (size_t)row * Nc + col) = make_float2(acc[ma][na][0], acc[ma][na][1]);
            if (row + 8 < M)
                *(float2*)(C + (size_t)(row + 8) * Nc + col) = make_float2(acc[ma][na][2], acc[ma][na][3]);
        }
    }

    // ---- fused attention dots: tile = exactly one head (Ch == 128) ----
    {
        const int head = colBase >> 7;
        const float* avh = av + (size_t)head * 128;
        const float* adh = adv + (size_t)head * 128;
        #pragma unroll
        for (int ma = 0; ma < 2; ma++) {
            float pe0 = 0.f, pd0 = 0.f, pe1 = 0.f, pd1 = 0.f;
            #pragma unroll
            for (int na = 0; na < 8; na++) {
                int cl = wn * 64 + na * 8 + t * 2;
                float w0 = avh[cl], w1 = avh[cl + 1];
                float d0 = adh[cl], d1 = adh[cl + 1];
                pe0 += acc[ma][na][0] * w0 + acc[ma][na][1] * w1;
                pd0 += acc[ma][na][0] * d0 + acc[ma][na][1] * d1;
                pe1 += acc[ma][na][2] * w0 + acc[ma][na][3] * w1;
                pd1 += acc[ma][na][2] * d0 + acc[ma][na][3] * d1;
            }
            #pragma unroll
            for (int o = 1; o <= 2; o <<= 1) {
                pe0 += __shfl_xor_sync(0xffffffff, pe0, o);
                pd0 += __shfl_xor_sync(0xffffffff, pd0, o);
                pe1 += __shfl_xor_sync(0xffffffff, pe1, o);
                pd1 += __shfl_xor_sync(0xffffffff, pd1, o);
            }
            if (t == 0) {
                int r = rowBase + wm * 32 + ma * 16 + g;
                if (r < M) {
                    atomicAdd(&esOut[(size_t)r * H + head], pe0);
                    atomicAdd(&edOut[(size_t)r * H + head], pd0);
                }
                if (r + 8 < M) {
                    atomicAdd(&esOut[(size_t)(r + 8) * H + head], pe1);
                    atomicAdd(&edOut[(size_t)(r + 8) * H + head], pd1);
                }
            }
        }
    }
}

// ================= graph kernels =============================================
__global__ void edge_w(int ET, int H) {
    int tdx = blockIdx.x * blockDim.x + threadIdx.x;
    if (tdx >= ET * H) return;
    int eid = tdx / H, hh = tdx - eid * H;
    float e = g_es[(size_t)g_src[eid] * H + hh] + g_ed[(size_t)g_dst[eid] * H + hh];
    e = e > 0.f ? e : 0.2f * e;
    g_w[tdx] = expf(e);
}

// CSR aggregate + bias + ELU + bf16 hi/lo split (layers 1-2)
__global__ void agg_split(const float* __restrict__ h, const float* __restrict__ b,
                          __nv_bfloat16* __restrict__ hi, __nv_bfloat16* __restrict__ lo,
                          int N, int H, int C) {
    int wid = (blockIdx.x * blockDim.x + threadIdx.x) >> 5;
    int lane = threadIdx.x & 31;
    if (wid >= N * H) return;
    int d = wid / H, hh = wid - d * H;
    int e0 = g_roff[d], e1 = g_roff[d + 1];

    float z = 0.f;
    for (int e = e0 + lane; e < e1; e += 32) z += g_w[(size_t)g_eid[e] * H + hh];
    #pragma unroll
    for (int o = 16; o; o >>= 1) z += __shfl_xor_sync(0xffffffff, z, o);
    float invz = 1.f / (z + 1e-16f);

    float acc[4] = {0.f, 0.f, 0.f, 0.f};
    const int nj = C >> 5;
    for (int e = e0; e < e1; e++) {
        int id = g_eid[e];
        float alpha = g_w[(size_t)id * H + hh] * invz;
        const float* hp = h + (size_t)g_src[id] * H * C + (size_t)hh * C;
        #pragma unroll
        for (int j = 0; j < 4; j++)
            if (j < nj) acc[j] += alpha * hp[lane + 32 * j];
    }
    size_t obase = (size_t)d * H * C + (size_t)hh * C;
    #pragma unroll
    for (int j = 0; j < 4; j++) {
        if (j >= nj) break;
        int c = lane + 32 * j;
        float v = acc[j] + b[hh * C + c];
        v = v > 0.f ? v : expm1f(v);
        __nv_bfloat16 hv = __float2bfloat16(v);
        hi[obase + c] = hv;
        lo[obase + c] = __float2bfloat16(v - __bfloat162float(hv));
    }
}

// CSR aggregate + bias + ELU + risk head (layer 3) -> d_out
__global__ void agg_risk(const float* __restrict__ h, const float* __restrict__ b,
                         const float* __restrict__ Wr, const float* __restrict__ br,
                         float* __restrict__ out, int N) {
    int wid = (blockIdx.x * blockDim.x + threadIdx.x) >> 5;
    int lane = threadIdx.x & 31;
    if (wid >= N) return;
    int d = wid;
    int e0 = g_roff[d], e1 = g_roff[d + 1];

    float z = 0.f;
    for (int e = e0 + lane; e < e1; e += 32) z += g_w[g_eid[e]];
    #pragma unroll
    for (int o = 16; o; o >>= 1) z += __shfl_xor_sync(0xffffffff, z, o);
    float invz = 1.f / (z + 1e-16f);

    float a0 = 0.f, a1 = 0.f;
    for (int e = e0; e < e1; e++) {
        int id = g_eid[e];
        float alpha = g_w[id] * invz;
        const float* hp = h + (size_t)g_src[id] * 64;
        a0 += alpha * hp[lane];
        a1 += alpha * hp[lane + 32];
    }
    float v0 = a0 + b[lane];        v0 = v0 > 0.f ? v0 : expm1f(v0);
    float v1 = a1 + b[lane + 32];   v1 = v1 > 0.f ? v1 : expm1f(v1);
    float s = v0 * Wr[lane] + v1 * Wr[lane + 32];
    #pragma unroll
    for (int o = 16; o; o >>= 1) s += __shfl_xor_sync(0xffffffff, s, o);
    if (lane == 0) out[d] = 1.f / (1.f + expf(-(s + br[0])));
}

// ================= launch ====================================================
extern "C" void kernel_launch(void* const* d_in, const int* in_sizes, int n_in,
                              void* d_out, int out_size) {
    const float* x   = (const float*)d_in[0];
    const void*  ei  = d_in[1];
    const float* W1  = (const float*)d_in[2];
    const float* as1 = (const float*)d_in[3];
    const float* ad1 = (const float*)d_in[4];
    const float* b1  = (const float*)d_in[5];
    const float* W2  = (const float*)d_in[6];
    const float* as2 = (const float*)d_in[7];
    const float* ad2 = (const float*)d_in[8];
    const float* b2  = (const float*)d_in[9];
    const float* W3  = (const float*)d_in[10];
    const float* as3 = (const float*)d_in[11];
    const float* ad3 = (const float*)d_in[12];
    const float* b3  = (const float*)d_in[13];
    const float* Wr  = (const float*)d_in[14];
    const float* br  = (const float*)d_in[15];

    const int N  = in_sizes[0] / 66;
    const int E  = in_sizes[1] / 2;
    const int ET = E + N;
    const int nb = (N + SCAN_B - 1) / SCAN_B;

    cudaFuncSetAttribute(gemm_mma64,  cudaFuncAttributeMaxDynamicSharedMemorySize, SMEM_G64);
    cudaFuncSetAttribute(gemm_mma128, cudaFuncAttributeMaxDynamicSharedMemorySize, SMEM_G128);

    void *p_h, *p_es, *p_ed, *p_wh, *p_wl, *p_ah, *p_al, *p_cnt;
    cudaGetSymbolAddress(&p_h,  g_h1);
    cudaGetSymbolAddress(&p_es, g_es);
    cudaGetSymbolAddress(&p_ed, g_ed);
    cudaGetSymbolAddress(&p_wh, g_wth);
    cudaGetSymbolAddress(&p_wl, g_wtl);
    cudaGetSymbolAddress(&p_ah, g_ah);
    cudaGetSymbolAddress(&p_al, g_al);
    cudaGetSymbolAddress(&p_cnt, g_cnt);

    float* h  = (float*)p_h;
    float* es = (float*)p_es; float* ed = (float*)p_ed;
    __nv_bfloat16* wh = (__nv_bfloat16*)p_wh;
    __nv_bfloat16* wl = (__nv_bfloat16*)p_wl;
    __nv_bfloat16* ah = (__nv_bfloat16*)p_ah;
    __nv_bfloat16* al = (__nv_bfloat16*)p_al;

    const int rowTiles = (N + 127) / 128;

    // ---- edges + CSR (built once) ----
    detect_dtype<<<1, 32>>>(ei, N);
    prep_edges<<<(ET + 255) / 256, 256>>>(ei, E, ET);
    cudaMemsetAsync(p_cnt, 0, N * sizeof(int));
    csr_hist<<<(ET + 255) / 256, 256>>>(ET);
    scan1<<<nb, SCAN_B>>>(N);
    scan2<<<1, 64>>>(nb);
    scan3<<<nb, SCAN_B>>>(N, ET);
    csr_fill<<<(ET + 255) / 256, 256>>>(ET);

    // ---------------- layer 1: 66 -> 8x128 (Nc=1024, Kpad=128, H=8, C=128) --
    cudaMemsetAsync(p_es, 0, (size_t)N * 8 * sizeof(float));
    cudaMemsetAsync(p_ed, 0, (size_t)N * 8 * sizeof(float));
    split_x<<<((N * 128) + 255) / 256, 256>>>(x, ah, al, N, 66, 128);
    prep_w<<<(1024 * 128 + 255) / 256, 256>>>(W1, wh, wl, 66, 1024, 128);
    {
        dim3 g(1024 / 128, rowTiles);
        gemm_mma128<<<g, 256, SMEM_G128>>>(ah, al, wh, wl, h, N, 128, 1024,
                                           as1, ad1, es, ed, 8);
    }
    edge_w<<<(ET * 8 + 255) / 256, 256>>>(ET, 8);
    agg_split<<<(N * 8 + 7) / 8, 256>>>(h, b1, ah, al, N, 8, 128);

    // ---------------- layer 2: 1024 -> 128 (Nc=128, Kpad=1024, H=1, C=128) ---
    cudaMemsetAsync(p_es, 0, (size_t)N * sizeof(float));
    cudaMemsetAsync(p_ed, 0, (size_t)N * sizeof(float));
    prep_w<<<(128 * 1024 + 255) / 256, 256>>>(W2, wh, wl, 1024, 128, 1024);
    {
        dim3 g(1, rowTiles);
        gemm_mma128<<<g, 256, SMEM_G128>>>(ah, al, wh, wl, h, N, 1024, 128,
                                           as2, ad2, es, ed, 1);
    }
    edge_w<<<(ET + 255) / 256, 256>>>(ET, 1);
    agg_split<<<(N + 7) / 8, 256>>>(h, b2, ah, al, N, 1, 128);

    // ---------------- layer 3: 128 -> 64 (Nc=64, Kpad=128, H=1, C=64) --------
    cudaMemsetAsync(p_es, 0, (size_t)N * sizeof(float));
    cudaMemsetAsync(p_ed, 0, (size_t)N * sizeof(float));
    prep_w<<<(64 * 128 + 255) / 256, 256>>>(W3, wh, wl, 128, 64, 128);
    {
        dim3 g(1, rowTiles);
        gemm_mma64<<<g, 256, SMEM_G64>>>(ah, al, wh, wl, h, N, 128, 64,
                                         as3, ad3, es, ed, 1, 64);
    }
    edge_w<<<(ET + 255) / 256, 256>>>(ET, 1);
    agg_risk<<<(N + 7) / 8, 256>>>(h, b3, Wr, br, (float*)d_out, N);
}

// round 14
// speedup vs baseline: 1.3656x; 1.3656x over previous
#include <cuda_runtime.h>
#include <cuda_bf16.h>
#include <math.h>
#include <stdint.h>

#define NMAX 50000
#define EMAX 200000
#define ETMAX (NMAX + EMAX)

// ---------------- scratch (device globals; no allocations allowed) ----------
__device__ float g_h1[(size_t)NMAX * 1024];   // GEMM outputs (h), reused per layer
__device__ float g_es[(size_t)NMAX * 8];
__device__ float g_ed[(size_t)NMAX * 8];
__device__ float g_w [(size_t)ETMAX * 8];
__device__ int   g_src[ETMAX];
__device__ int   g_dst[ETMAX];
__device__ int   g_is64;
// CSR by dst
__device__ int   g_cnt[NMAX];
__device__ int   g_roff[NMAX + 1];
__device__ int   g_pos[NMAX];
__device__ int   g_bsum[64];
__device__ int   g_eid[ETMAX];
// pre-split A operand (hi/lo bf16), [N][Kpad]
__device__ __nv_bfloat16 g_ah[(size_t)NMAX * 1024];
__device__ __nv_bfloat16 g_al[(size_t)NMAX * 1024];
// transposed + hi/lo-split weights, [Nc][Kpad] bf16
__device__ __nv_bfloat16 g_wth[131072];
__device__ __nv_bfloat16 g_wtl[131072];

// ================= edge preprocessing =======================================
__global__ void detect_dtype(const void* ei, int N) {
    if (blockIdx.x == 0 && threadIdx.x == 0) {
        const long long* p = (const long long*)ei;
        int ok = 1;
        for (int i = 0; i < 64; i++) {
            long long v = p[i];
            if (v < 0 || v >= (long long)N) { ok = 0; break; }
        }
        g_is64 = ok;
    }
}
__global__ void prep_edges(const void* ei, int E, int ET) {
    int i = blockIdx.x * blockDim.x + threadIdx.x;
    if (i >= ET) return;
    int s, d;
    if (i < E) {
        if (g_is64) { const long long* p = (const long long*)ei; s = (int)p[i]; d = (int)p[E + i]; }
        else        { const int* p = (const int*)ei; s = p[i]; d = p[E + i]; }
    } else { s = d = i - E; }
    g_src[i] = s; g_dst[i] = d;
}

// ---------------- CSR build --------------------------------------------------
__global__ void csr_hist(int ET) {
    int i = blockIdx.x * blockDim.x + threadIdx.x;
    if (i < ET) atomicAdd(&g_cnt[g_dst[i]], 1);
}
#define SCAN_B 1024
__global__ void scan1(int n) {
    __shared__ int sh[SCAN_B];
    int gid = blockIdx.x * SCAN_B + threadIdx.x;
    int v = (gid < n) ? g_cnt[gid] : 0;
    sh[threadIdx.x] = v;
    __syncthreads();
    for (int o = 1; o < SCAN_B; o <<= 1) {
        int t = (threadIdx.x >= o) ? sh[threadIdx.x - o] : 0;
        __syncthreads();
        sh[threadIdx.x] += t;
        __syncthreads();
    }
    if (gid < n) g_roff[gid] = sh[threadIdx.x] - v;   // exclusive
    if (threadIdx.x == SCAN_B - 1) g_bsum[blockIdx.x] = sh[threadIdx.x];
}
__global__ void scan2(int nb) {
    __shared__ int sh[64];
    int v = (threadIdx.x < nb) ? g_bsum[threadIdx.x] : 0;
    sh[threadIdx.x] = v;
    __syncthreads();
    for (int o = 1; o < 64; o <<= 1) {
        int t = (threadIdx.x >= o) ? sh[threadIdx.x - o] : 0;
        __syncthreads();
        sh[threadIdx.x] += t;
        __syncthreads();
    }
    if (threadIdx.x < nb) g_bsum[threadIdx.x] = sh[threadIdx.x] - v;
}
__global__ void scan3(int n, int ET) {
    int gid = blockIdx.x * SCAN_B + threadIdx.x;
    if (gid < n) {
        int v = g_roff[gid] + g_bsum[blockIdx.x];
        g_roff[gid] = v;
        g_pos[gid] = v;
    }
    if (gid == 0) g_roff[n] = ET;
}
__global__ void csr_fill(int ET) {
    int i = blockIdx.x * blockDim.x + threadIdx.x;
    if (i >= ET) return;
    int slot = atomicAdd(&g_pos[g_dst[i]], 1);
    g_eid[slot] = i;
}

// ---------------- weight / input prep ---------------------------------------
__global__ void prep_w(const float* __restrict__ W, __nv_bfloat16* __restrict__ hi,
                       __nv_bfloat16* __restrict__ lo, int K, int N, int Kpad) {
    int idx = blockIdx.x * blockDim.x + threadIdx.x;
    if (idx >= N * Kpad) return;
    int n = idx / Kpad, k = idx - n * Kpad;
    float v = (k < K) ? W[(size_t)k * N + n] : 0.f;
    __nv_bfloat16 h = __float2bfloat16(v);
    hi[idx] = h;
    lo[idx] = __float2bfloat16(v - __bfloat162float(h));
}
__global__ void split_x(const float* __restrict__ x, __nv_bfloat16* __restrict__ hi,
                        __nv_bfloat16* __restrict__ lo, int N, int K, int Kpad) {
    int idx = blockIdx.x * blockDim.x + threadIdx.x;
    if (idx >= N * Kpad) return;
    int n = idx / Kpad, k = idx - n * Kpad;
    float v = (k < K) ? x[(size_t)n * K + k] : 0.f;
    __nv_bfloat16 h = __float2bfloat16(v);
    hi[idx] = h;
    lo[idx] = __float2bfloat16(v - __bfloat162float(h));
}

// ================= mma.sync bf16-split GEMM (exact R8 config) ================
#define APAD 72
#define SMEM_GEMM ((128 * APAD * 2 + 64 * APAD * 2) * 2)   // 55296 bytes

__device__ __forceinline__ void mma_bf16(float* c, uint32_t a0, uint32_t a1,
                                         uint32_t a2, uint32_t a3,
                                         uint32_t b0, uint32_t b1) {
    asm volatile(
        "mma.sync.aligned.m16n8k16.row.col.f32.bf16.bf16.f32 "
        "{%0,%1,%2,%3}, {%4,%5,%6,%7}, {%8,%9}, {%0,%1,%2,%3};"
        : "+f"(c[0]), "+f"(c[1]), "+f"(c[2]), "+f"(c[3])
        : "r"(a0), "r"(a1), "r"(a2), "r"(a3), "r"(b0), "r"(b1));
}

__global__ void __launch_bounds__(256, 2)
gemm_mma(const __nv_bfloat16* __restrict__ Ah, const __nv_bfloat16* __restrict__ Al,
         const __nv_bfloat16* __restrict__ Bh, const __nv_bfloat16* __restrict__ Bl,
         float* __restrict__ C, int M, int Kpad, int Nc,
         const float* __restrict__ av, const float* __restrict__ adv,
         float* __restrict__ esOut, float* __restrict__ edOut, int H, int Ch) {
    extern __shared__ __nv_bfloat16 sm[];
    __nv_bfloat16* sAh = sm;
    __nv_bfloat16* sAl = sAh + 128 * APAD;
    __nv_bfloat16* sBh = sAl + 128 * APAD;
    __nv_bfloat16* sBl = sBh + 64 * APAD;

    const int tid = threadIdx.x;
    const int rowBase = blockIdx.y * 128, colBase = blockIdx.x * 64;
    const int warp = tid >> 5, lane = tid & 31;
    const int wm = warp & 3, wn = warp >> 2;
    const int g = lane >> 2, t = lane & 3;

    float acc[2][4][4] = {};

    for (int k0 = 0; k0 < Kpad; k0 += 64) {
        #pragma unroll
        for (int i = 0; i < 4; i++) {
            int lin = tid + (i << 8);
            int row = lin >> 3, u = lin & 7;
            int gr = rowBase + row;
            int e = row * APAD + (u << 3);
            uint4 hv = make_uint4(0, 0, 0, 0), lv = make_uint4(0, 0, 0, 0);
            if (gr < M) {
                size_t gidx = (size_t)gr * Kpad + k0 + (u << 3);
                hv = *(const uint4*)(Ah + gidx);
                lv = *(const uint4*)(Al + gidx);
            }
            *(uint4*)(sAh + e) = hv;
            *(uint4*)(sAl + e) = lv;
        }
        #pragma unroll
        for (int i = 0; i < 2; i++) {
            int lin = tid + (i << 8);
            int n = lin >> 3, u = lin & 7;
            size_t gidx = (size_t)(colBase + n) * Kpad + k0 + (u << 3);
            int e = n * APAD + (u << 3);
            *(uint4*)(sBh + e) = *(const uint4*)(Bh + gidx);
            *(uint4*)(sBl + e) = *(const uint4*)(Bl + gidx);
        }
        __syncthreads();

        #pragma unroll
        for (int ks = 0; ks < 4; ks++) {
            const int kc = ks * 16 + t * 2;
            uint32_t ah[2][4], al[2][4];
            #pragma unroll
            for (int ma = 0; ma < 2; ma++) {
                int r0 = wm * 32 + ma * 16 + g;
                ah[ma][0] = *(const uint32_t*)(sAh + r0 * APAD + kc);
                ah[ma][1] = *(const uint32_t*)(sAh + (r0 + 8) * APAD + kc);
                ah[ma][2] = *(const uint32_t*)(sAh + r0 * APAD + kc + 8);
                ah[ma][3] = *(const uint32_t*)(sAh + (r0 + 8) * APAD + kc + 8);
                al[ma][0] = *(const uint32_t*)(sAl + r0 * APAD + kc);
                al[ma][1] = *(const uint32_t*)(sAl + (r0 + 8) * APAD + kc);
                al[ma][2] = *(const uint32_t*)(sAl + r0 * APAD + kc + 8);
                al[ma][3] = *(const uint32_t*)(sAl + (r0 + 8) * APAD + kc + 8);
            }
            #pragma unroll
            for (int na = 0; na < 4; na++) {
                int n0 = wn * 32 + na * 8 + g;
                uint32_t bh0 = *(const uint32_t*)(sBh + n0 * APAD + kc);
                uint32_t bh1 = *(const uint32_t*)(sBh + n0 * APAD + kc + 8);
                uint32_t bl0 = *(const uint32_t*)(sBl + n0 * APAD + kc);
                uint32_t bl1 = *(const uint32_t*)(sBl + n0 * APAD + kc + 8);
                #pragma unroll
                for (int ma = 0; ma < 2; ma++) {
                    mma_bf16(acc[ma][na], ah[ma][0], ah[ma][1], ah[ma][2], ah[ma][3], bh0, bh1);
                    mma_bf16(acc[ma][na], ah[ma][0], ah[ma][1], ah[ma][2], ah[ma][3], bl0, bl1);
                    mma_bf16(acc[ma][na], al[ma][0], al[ma][1], al[ma][2], al[ma][3], bh0, bh1);
                }
            }
        }
        __syncthreads();
    }

    #pragma unroll
    for (int ma = 0; ma < 2; ma++) {
        int row = rowBase + wm * 32 + ma * 16 + g;
        #pragma unroll
        for (int na = 0; na < 4; na++) {
            int col = colBase + wn * 32 + na * 8 + t * 2;
            if (row < M)
                *(float2*)(C + (size_t)row * Nc + col) = make_float2(acc[ma][na][0], acc[ma][na][1]);
            if (row + 8 < M)
                *(float2*)(C + (size_t)(row + 8) * Nc + col) = make_float2(acc[ma][na][2], acc[ma][na][3]);
        }
    }

    // ---- fused attention dots (tile cols lie in ONE head) ----
    {
        const int head = colBase / Ch;
        const int cb = colBase - head * Ch;
        const float* avh = av + head * Ch + cb;
        const float* adh = adv + head * Ch + cb;
        #pragma unroll
        for (int ma = 0; ma < 2; ma++) {
            float pe0 = 0.f, pd0 = 0.f, pe1 = 0.f, pd1 = 0.f;
            #pragma unroll
            for (int na = 0; na < 4; na++) {
                int cl = wn * 32 + na * 8 + t * 2;
                float w0 = avh[cl], w1 = avh[cl + 1];
                float d0 = adh[cl], d1 = adh[cl + 1];
                pe0 += acc[ma][na][0] * w0 + acc[ma][na][1] * w1;
                pd0 += acc[ma][na][0] * d0 + acc[ma][na][1] * d1;
                pe1 += acc[ma][na][2] * w0 + acc[ma][na][3] * w1;
                pd1 += acc[ma][na][2] * d0 + acc[ma][na][3] * d1;
            }
            #pragma unroll
            for (int o = 1; o <= 2; o <<= 1) {
                pe0 += __shfl_xor_sync(0xffffffff, pe0, o);
                pd0 += __shfl_xor_sync(0xffffffff, pd0, o);
                pe1 += __shfl_xor_sync(0xffffffff, pe1, o);
                pd1 += __shfl_xor_sync(0xffffffff, pd1, o);
            }
            if (t == 0) {
                int r = rowBase + wm * 32 + ma * 16 + g;
                if (r < M) {
                    atomicAdd(&esOut[(size_t)r * H + head], pe0);
                    atomicAdd(&edOut[(size_t)r * H + head], pd0);
                }
                if (r + 8 < M) {
                    atomicAdd(&esOut[(size_t)(r + 8) * H + head], pe1);
                    atomicAdd(&edOut[(size_t)(r + 8) * H + head], pd1);
                }
            }
        }
    }
}

// ================= graph kernels =============================================
__global__ void edge_w(int ET, int H) {
    int tdx = blockIdx.x * blockDim.x + threadIdx.x;
    if (tdx >= ET * H) return;
    int eid = tdx / H, hh = tdx - eid * H;
    float e = g_es[(size_t)g_src[eid] * H + hh] + g_ed[(size_t)g_dst[eid] * H + hh];
    e = e > 0.f ? e : 0.2f * e;
    g_w[tdx] = expf(e);
}

// CSR aggregate + bias + ELU + bf16 split (layers 1-2, C == 128)
// shfl-broadcast edge metadata + float4 h gathers
__global__ void agg_split(const float* __restrict__ h, const float* __restrict__ b,
                          __nv_bfloat16* __restrict__ hi, __nv_bfloat16* __restrict__ lo,
                          int N, int H) {
    int wid = (blockIdx.x * blockDim.x + threadIdx.x) >> 5;
    int lane = threadIdx.x & 31;
    if (wid >= N * H) return;
    int d = wid / H, hh = wid - d * H;
    int e0 = g_roff[d], e1 = g_roff[d + 1];

    float4 acc = make_float4(0.f, 0.f, 0.f, 0.f);
    float z = 0.f;

    for (int base = e0; base < e1; base += 32) {
        int e = base + lane;
        int sv = 0; float wv = 0.f;
        if (e < e1) {
            int id = g_eid[e];
            sv = g_src[id];
            wv = g_w[(size_t)id * H + hh];
        }
        z += wv;
        int m = min(32, e1 - base);
        for (int j = 0; j < m; j++) {
            int s = __shfl_sync(0xffffffff, sv, j);
            float wj = __shfl_sync(0xffffffff, wv, j);
            const float4* hp = (const float4*)(h + (size_t)s * H * 128 + (size_t)hh * 128);
            float4 v = hp[lane];
            acc.x += wj * v.x; acc.y += wj * v.y;
            acc.z += wj * v.z; acc.w += wj * v.w;
        }
    }
    #pragma unroll
    for (int o = 16; o; o >>= 1) z += __shfl_xor_sync(0xffffffff, z, o);
    float invz = 1.f / (z + 1e-16f);

    const float4 bv = *(const float4*)(b + hh * 128 + lane * 4);
    float v0 = acc.x * invz + bv.x;  v0 = v0 > 0.f ? v0 : expm1f(v0);
    float v1 = acc.y * invz + bv.y;  v1 = v1 > 0.f ? v1 : expm1f(v1);
    float v2 = acc.z * invz + bv.z;  v2 = v2 > 0.f ? v2 : expm1f(v2);
    float v3 = acc.w * invz + bv.w;  v3 = v3 > 0.f ? v3 : expm1f(v3);

    __nv_bfloat162 h01, h23, l01, l23;
    h01.x = __float2bfloat16(v0); h01.y = __float2bfloat16(v1);
    h23.x = __float2bfloat16(v2); h23.y = __float2bfloat16(v3);
    l01.x = __float2bfloat16(v0 - __bfloat162float(h01.x));
    l01.y = __float2bfloat16(v1 - __bfloat162float(h01.y));
    l23.x = __float2bfloat16(v2 - __bfloat162float(h23.x));
    l23.y = __float2bfloat16(v3 - __bfloat162float(h23.y));

    size_t obase = (size_t)d * H * 128 + (size_t)hh * 128 + lane * 4;
    *(uint2*)(hi + obase) = make_uint2(*(uint32_t*)&h01, *(uint32_t*)&h23);
    *(uint2*)(lo + obase) = make_uint2(*(uint32_t*)&l01, *(uint32_t*)&l23);
}

// CSR aggregate + bias + ELU + risk head (layer 3, H=1, C=64) -> d_out
__global__ void agg_risk(const float* __restrict__ h, const float* __restrict__ b,
                         const float* __restrict__ Wr, const float* __restrict__ br,
                         float* __restrict__ out, int N) {
    int wid = (blockIdx.x * blockDim.x + threadIdx.x) >> 5;
    int lane = threadIdx.x & 31;
    if (wid >= N) return;
    int d = wid;
    int e0 = g_roff[d], e1 = g_roff[d + 1];

    float a0 = 0.f, a1 = 0.f, z = 0.f;
    for (int base = e0; base < e1; base += 32) {
        int e = base + lane;
        int sv = 0; float wv = 0.f;
        if (e < e1) {
            int id = g_eid[e];
            sv = g_src[id];
            wv = g_w[id];
        }
        z += wv;
        int m = min(32, e1 - base);
        for (int j = 0; j < m; j++) {
            int s = __shfl_sync(0xffffffff, sv, j);
            float wj = __shfl_sync(0xffffffff, wv, j);
            const float2* hp = (const float2*)(h + (size_t)s * 64);
            float2 v = hp[lane];
            a0 += wj * v.x; a1 += wj * v.y;
        }
    }
    #pragma unroll
    for (int o = 16; o; o >>= 1) z += __shfl_xor_sync(0xffffffff, z, o);
    float invz = 1.f / (z + 1e-16f);

    float v0 = a0 * invz + b[lane * 2];      v0 = v0 > 0.f ? v0 : expm1f(v0);
    float v1 = a1 * invz + b[lane * 2 + 1];  v1 = v1 > 0.f ? v1 : expm1f(v1);
    float s = v0 * Wr[lane * 2] + v1 * Wr[lane * 2 + 1];
    #pragma unroll
    for (int o = 16; o; o >>= 1) s += __shfl_xor_sync(0xffffffff, s, o);
    if (lane == 0) out[d] = 1.f / (1.f + expf(-(s + br[0])));
}

// ================= launch ====================================================
extern "C" void kernel_launch(void* const* d_in, const int* in_sizes, int n_in,
                              void* d_out, int out_size) {
    const float* x   = (const float*)d_in[0];
    const void*  ei  = d_in[1];
    const float* W1  = (const float*)d_in[2];
    const float* as1 = (const float*)d_in[3];
    const float* ad1 = (const float*)d_in[4];
    const float* b1  = (const float*)d_in[5];
    const float* W2  = (const float*)d_in[6];
    const float* as2 = (const float*)d_in[7];
    const float* ad2 = (const float*)d_in[8];
    const float* b2  = (const float*)d_in[9];
    const float* W3  = (const float*)d_in[10];
    const float* as3 = (const float*)d_in[11];
    const float* ad3 = (const float*)d_in[12];
    const float* b3  = (const float*)d_in[13];
    const float* Wr  = (const float*)d_in[14];
    const float* br  = (const float*)d_in[15];

    const int N  = in_sizes[0] / 66;
    const int E  = in_sizes[1] / 2;
    const int ET = E + N;
    const int nb = (N + SCAN_B - 1) / SCAN_B;

    cudaFuncSetAttribute(gemm_mma, cudaFuncAttributeMaxDynamicSharedMemorySize, SMEM_GEMM);

    void *p_h, *p_es, *p_ed, *p_wh, *p_wl, *p_ah, *p_al, *p_cnt;
    cudaGetSymbolAddress(&p_h,  g_h1);
    cudaGetSymbolAddress(&p_es, g_es);
    cudaGetSymbolAddress(&p_ed, g_ed);
    cudaGetSymbolAddress(&p_wh, g_wth);
    cudaGetSymbolAddress(&p_wl, g_wtl);
    cudaGetSymbolAddress(&p_ah, g_ah);
    cudaGetSymbolAddress(&p_al, g_al);
    cudaGetSymbolAddress(&p_cnt, g_cnt);

    float* h  = (float*)p_h;
    float* es = (float*)p_es; float* ed = (float*)p_ed;
    __nv_bfloat16* wh = (__nv_bfloat16*)p_wh;
    __nv_bfloat16* wl = (__nv_bfloat16*)p_wl;
    __nv_bfloat16* ah = (__nv_bfloat16*)p_ah;
    __nv_bfloat16* al = (__nv_bfloat16*)p_al;

    const int rowTiles = (N + 127) / 128;

    // ---- edges + CSR (built once) ----
    detect_dtype<<<1, 32>>>(ei, N);
    prep_edges<<<(ET + 255) / 256, 256>>>(ei, E, ET);
    cudaMemsetAsync(p_cnt, 0, N * sizeof(int));
    csr_hist<<<(ET + 255) / 256, 256>>>(ET);
    scan1<<<nb, SCAN_B>>>(N);
    scan2<<<1, 64>>>(nb);
    scan3<<<nb, SCAN_B>>>(N, ET);
    csr_fill<<<(ET + 255) / 256, 256>>>(ET);

    // ---------------- layer 1: 66 -> 8x128 (Nc=1024, Kpad=128, H=8, C=128) --
    cudaMemsetAsync(p_es, 0, (size_t)N * 8 * sizeof(float));
    cudaMemsetAsync(p_ed, 0, (size_t)N * 8 * sizeof(float));
    split_x<<<((N * 128) + 255) / 256, 256>>>(x, ah, al, N, 66, 128);
    prep_w<<<(1024 * 128 + 255) / 256, 256>>>(W1, wh, wl, 66, 1024, 128);
    {
        dim3 g(1024 / 64, rowTiles);
        gemm_mma<<<g, 256, SMEM_GEMM>>>(ah, al, wh, wl, h, N, 128, 1024,
                                        as1, ad1, es, ed, 8, 128);
    }
    edge_w<<<(ET * 8 + 255) / 256, 256>>>(ET, 8);
    agg_split<<<(N * 8 + 7) / 8, 256>>>(h, b1, ah, al, N, 8);

    // ---------------- layer 2: 1024 -> 128 (Nc=128, Kpad=1024, H=1, C=128) ---
    cudaMemsetAsync(p_es, 0, (size_t)N * sizeof(float));
    cudaMemsetAsync(p_ed, 0, (size_t)N * sizeof(float));
    prep_w<<<(128 * 1024 + 255) / 256, 256>>>(W2, wh, wl, 1024, 128, 1024);
    {
        dim3 g(128 / 64, rowTiles);
        gemm_mma<<<g, 256, SMEM_GEMM>>>(ah, al, wh, wl, h, N, 1024, 128,
                                        as2, ad2, es, ed, 1, 128);
    }
    edge_w<<<(ET + 255) / 256, 256>>>(ET, 1);
    agg_split<<<(N + 7) / 8, 256>>>(h, b2, ah, al, N, 1);

    // ---------------- layer 3: 128 -> 64 (Nc=64, Kpad=128, H=1, C=64) --------
    cudaMemsetAsync(p_es, 0, (size_t)N * sizeof(float));
    cudaMemsetAsync(p_ed, 0, (size_t)N * sizeof(float));
    prep_w<<<(64 * 128 + 255) / 256, 256>>>(W3, wh, wl, 128, 64, 128);
    {
        dim3 g(1, rowTiles);
        gemm_mma<<<g, 256, SMEM_GEMM>>>(ah, al, wh, wl, h, N, 128, 64,
                                        as3, ad3, es, ed, 1, 64);
    }
    edge_w<<<(ET + 255) / 256, 256>>>(ET, 1);
    agg_risk<<<(N + 7) / 8, 256>>>(h, b3, Wr, br, (float*)d_out, N);
}

// round 15
// speedup vs baseline: 1.3993x; 1.0246x over previous
#include <cuda_runtime.h>
#include <cuda_bf16.h>
#include <math.h>
#include <stdint.h>

#define NMAX 50000
#define EMAX 200000
#define ETMAX (NMAX + EMAX)

// ---------------- scratch (device globals; no allocations allowed) ----------
__device__ float g_h1[(size_t)NMAX * 1024];   // GEMM outputs (h), reused per layer
__device__ float g_es[(size_t)NMAX * 8];
__device__ float g_ed[(size_t)NMAX * 8];
__device__ float g_w [(size_t)ETMAX * 8];
__device__ int   g_src[ETMAX];
__device__ int   g_dst[ETMAX];
__device__ int   g_is64;
// CSR by dst
__device__ int   g_cnt[NMAX];
__device__ int   g_roff[NMAX + 1];
__device__ int   g_pos[NMAX];
__device__ int   g_bsum[64];
__device__ int   g_eid[ETMAX];
// pre-split A operand (hi/lo bf16), [N][Kpad]
__device__ __nv_bfloat16 g_ah[(size_t)NMAX * 1024];
__device__ __nv_bfloat16 g_al[(size_t)NMAX * 1024];
// transposed + hi/lo-split weights, [Nc][Kpad] bf16
__device__ __nv_bfloat16 g_wth[131072];
__device__ __nv_bfloat16 g_wtl[131072];

// ================= edge preprocessing =======================================
__global__ void detect_dtype(const void* ei, int N) {
    if (blockIdx.x == 0 && threadIdx.x == 0) {
        const long long* p = (const long long*)ei;
        int ok = 1;
        for (int i = 0; i < 64; i++) {
            long long v = p[i];
            if (v < 0 || v >= (long long)N) { ok = 0; break; }
        }
        g_is64 = ok;
    }
}
__global__ void prep_edges(const void* ei, int E, int ET) {
    int i = blockIdx.x * blockDim.x + threadIdx.x;
    if (i >= ET) return;
    int s, d;
    if (i < E) {
        if (g_is64) { const long long* p = (const long long*)ei; s = (int)p[i]; d = (int)p[E + i]; }
        else        { const int* p = (const int*)ei; s = p[i]; d = p[E + i]; }
    } else { s = d = i - E; }
    g_src[i] = s; g_dst[i] = d;
}

// ---------------- CSR build --------------------------------------------------
__global__ void csr_hist(int ET) {
    int i = blockIdx.x * blockDim.x + threadIdx.x;
    if (i < ET) atomicAdd(&g_cnt[g_dst[i]], 1);
}
#define SCAN_B 1024
__global__ void scan1(int n) {
    __shared__ int sh[SCAN_B];
    int gid = blockIdx.x * SCAN_B + threadIdx.x;
    int v = (gid < n) ? g_cnt[gid] : 0;
    sh[threadIdx.x] = v;
    __syncthreads();
    for (int o = 1; o < SCAN_B; o <<= 1) {
        int t = (threadIdx.x >= o) ? sh[threadIdx.x - o] : 0;
        __syncthreads();
        sh[threadIdx.x] += t;
        __syncthreads();
    }
    if (gid < n) g_roff[gid] = sh[threadIdx.x] - v;   // exclusive
    if (threadIdx.x == SCAN_B - 1) g_bsum[blockIdx.x] = sh[threadIdx.x];
}
__global__ void scan2(int nb) {
    __shared__ int sh[64];
    int v = (threadIdx.x < nb) ? g_bsum[threadIdx.x] : 0;
    sh[threadIdx.x] = v;
    __syncthreads();
    for (int o = 1; o < 64; o <<= 1) {
        int t = (threadIdx.x >= o) ? sh[threadIdx.x - o] : 0;
        __syncthreads();
        sh[threadIdx.x] += t;
        __syncthreads();
    }
    if (threadIdx.x < nb) g_bsum[threadIdx.x] = sh[threadIdx.x] - v;
}
__global__ void scan3(int n, int ET) {
    int gid = blockIdx.x * SCAN_B + threadIdx.x;
    if (gid < n) {
        int v = g_roff[gid] + g_bsum[blockIdx.x];
        g_roff[gid] = v;
        g_pos[gid] = v;
    }
    if (gid == 0) g_roff[n] = ET;
}
__global__ void csr_fill(int ET) {
    int i = blockIdx.x * blockDim.x + threadIdx.x;
    if (i >= ET) return;
    int slot = atomicAdd(&g_pos[g_dst[i]], 1);
    g_eid[slot] = i;
}

// ---------------- weight / input prep ---------------------------------------
__global__ void prep_w(const float* __restrict__ W, __nv_bfloat16* __restrict__ hi,
                       __nv_bfloat16* __restrict__ lo, int K, int N, int Kpad) {
    int idx = blockIdx.x * blockDim.x + threadIdx.x;
    if (idx >= N * Kpad) return;
    int n = idx / Kpad, k = idx - n * Kpad;
    float v = (k < K) ? W[(size_t)k * N + n] : 0.f;
    __nv_bfloat16 h = __float2bfloat16(v);
    hi[idx] = h;
    lo[idx] = __float2bfloat16(v - __bfloat162float(h));
}
__global__ void split_x(const float* __restrict__ x, __nv_bfloat16* __restrict__ hi,
                        __nv_bfloat16* __restrict__ lo, int N, int K, int Kpad) {
    int idx = blockIdx.x * blockDim.x + threadIdx.x;
    if (idx >= N * Kpad) return;
    int n = idx / Kpad, k = idx - n * Kpad;
    float v = (k < K) ? x[(size_t)n * K + k] : 0.f;
    __nv_bfloat16 h = __float2bfloat16(v);
    hi[idx] = h;
    lo[idx] = __float2bfloat16(v - __bfloat162float(h));
}

// ================= mma.sync bf16-split GEMM (R8 config + ldmatrix) ===========
#define APAD 72
#define SMEM_GEMM ((128 * APAD * 2 + 64 * APAD * 2) * 2)   // 55296 bytes

__device__ __forceinline__ void mma_bf16(float* c, uint32_t a0, uint32_t a1,
                                         uint32_t a2, uint32_t a3,
                                         uint32_t b0, uint32_t b1) {
    asm volatile(
        "mma.sync.aligned.m16n8k16.row.col.f32.bf16.bf16.f32 "
        "{%0,%1,%2,%3}, {%4,%5,%6,%7}, {%8,%9}, {%0,%1,%2,%3};"
        : "+f"(c[0]), "+f"(c[1]), "+f"(c[2]), "+f"(c[3])
        : "r"(a0), "r"(a1), "r"(a2), "r"(a3), "r"(b0), "r"(b1));
}
__device__ __forceinline__ void ldmx4(uint32_t* r, uint32_t saddr) {
    asm volatile("ldmatrix.sync.aligned.m8n8.x4.shared.b16 {%0,%1,%2,%3}, [%4];"
                 : "=r"(r[0]), "=r"(r[1]), "=r"(r[2]), "=r"(r[3]) : "r"(saddr));
}

__global__ void __launch_bounds__(256, 2)
gemm_mma(const __nv_bfloat16* __restrict__ Ah, const __nv_bfloat16* __restrict__ Al,
         const __nv_bfloat16* __restrict__ Bh, const __nv_bfloat16* __restrict__ Bl,
         float* __restrict__ C, int M, int Kpad, int Nc,
         const float* __restrict__ av, const float* __restrict__ adv,
         float* __restrict__ esOut, float* __restrict__ edOut, int H, int Ch) {
    extern __shared__ __nv_bfloat16 sm[];
    __nv_bfloat16* sAh = sm;
    __nv_bfloat16* sAl = sAh + 128 * APAD;
    __nv_bfloat16* sBh = sAl + 128 * APAD;
    __nv_bfloat16* sBl = sBh + 64 * APAD;

    const uint32_t sAh32 = (uint32_t)__cvta_generic_to_shared(sAh);
    const uint32_t sAl32 = (uint32_t)__cvta_generic_to_shared(sAl);
    const uint32_t sBh32 = (uint32_t)__cvta_generic_to_shared(sBh);
    const uint32_t sBl32 = (uint32_t)__cvta_generic_to_shared(sBl);

    const int tid = threadIdx.x;
    const int rowBase = blockIdx.y * 128, colBase = blockIdx.x * 64;
    const int warp = tid >> 5, lane = tid & 31;
    const int wm = warp & 3, wn = warp >> 2;
    const int g = lane >> 2, t = lane & 3;
    const int lrow = lane & 7;

    // ldmatrix per-lane offsets (element units, before *2 bytes):
    // A (16x16 tile): m0=(r,k) m1=(r+8,k) m2=(r,k+8) m3=(r+8,k+8)
    const int aRowOff = lrow + ((lane >> 3) & 1) * 8;   // row within 16-row tile
    const int aColOff = (lane >> 4) * 8;                // k offset 0/8
    // B (16 n-rows x 16 k): m0=(n,k) m1=(n,k+8) m2=(n+8,k) m3=(n+8,k+8)
    const int bRowOff = lrow + (lane >> 4) * 8;
    const int bColOff = ((lane >> 3) & 1) * 8;

    float acc[2][4][4] = {};

    for (int k0 = 0; k0 < Kpad; k0 += 64) {
        #pragma unroll
        for (int i = 0; i < 4; i++) {
            int lin = tid + (i << 8);
            int row = lin >> 3, u = lin & 7;
            int gr = rowBase + row;
            int e = row * APAD + (u << 3);
            uint4 hv = make_uint4(0, 0, 0, 0), lv = make_uint4(0, 0, 0, 0);
            if (gr < M) {
                size_t gidx = (size_t)gr * Kpad + k0 + (u << 3);
                hv = *(const uint4*)(Ah + gidx);
                lv = *(const uint4*)(Al + gidx);
            }
            *(uint4*)(sAh + e) = hv;
            *(uint4*)(sAl + e) = lv;
        }
        #pragma unroll
        for (int i = 0; i < 2; i++) {
            int lin = tid + (i << 8);
            int n = lin >> 3, u = lin & 7;
            size_t gidx = (size_t)(colBase + n) * Kpad + k0 + (u << 3);
            int e = n * APAD + (u << 3);
            *(uint4*)(sBh + e) = *(const uint4*)(Bh + gidx);
            *(uint4*)(sBl + e) = *(const uint4*)(Bl + gidx);
        }
        __syncthreads();

        #pragma unroll
        for (int ks = 0; ks < 4; ks++) {
            const int kbase = ks * 16;
            uint32_t ah[2][4], al[2][4];
            #pragma unroll
            for (int ma = 0; ma < 2; ma++) {
                uint32_t off = (uint32_t)(((wm * 32 + ma * 16 + aRowOff) * APAD
                                           + kbase + aColOff) * 2);
                ldmx4(ah[ma], sAh32 + off);
                ldmx4(al[ma], sAl32 + off);
            }
            uint32_t bh[2][4], bl[2][4];
            #pragma unroll
            for (int p = 0; p < 2; p++) {
                uint32_t off = (uint32_t)(((wn * 32 + p * 16 + bRowOff) * APAD
                                           + kbase + bColOff) * 2);
                ldmx4(bh[p], sBh32 + off);
                ldmx4(bl[p], sBl32 + off);
            }
            #pragma unroll
            for (int na = 0; na < 4; na++) {
                // fragment regs: pair p = na>>1, within-pair idx q = na&1
                const int p = na >> 1, q = (na & 1) << 1;
                uint32_t bh0 = bh[p][q], bh1 = bh[p][q + 1];
                uint32_t bl0 = bl[p][q], bl1 = bl[p][q + 1];
                #pragma unroll
                for (int ma = 0; ma < 2; ma++) {
                    mma_bf16(acc[ma][na], ah[ma][0], ah[ma][1], ah[ma][2], ah[ma][3], bh0, bh1);
                    mma_bf16(acc[ma][na], ah[ma][0], ah[ma][1], ah[ma][2], ah[ma][3], bl0, bl1);
                    mma_bf16(acc[ma][na], al[ma][0], al[ma][1], al[ma][2], al[ma][3], bh0, bh1);
                }
            }
        }
        __syncthreads();
    }

    #pragma unroll
    for (int ma = 0; ma < 2; ma++) {
        int row = rowBase + wm * 32 + ma * 16 + g;
        #pragma unroll
        for (int na = 0; na < 4; na++) {
            int col = colBase + wn * 32 + na * 8 + t * 2;
            if (row < M)
                *(float2*)(C + (size_t)row * Nc + col) = make_float2(acc[ma][na][0], acc[ma][na][1]);
            if (row + 8 < M)
                *(float2*)(C + (size_t)(row + 8) * Nc + col) = make_float2(acc[ma][na][2], acc[ma][na][3]);
        }
    }

    // ---- fused attention dots (tile cols lie in ONE head) ----
    {
        const int head = colBase / Ch;
        const int cb = colBase - head * Ch;
        const float* avh = av + head * Ch + cb;
        const float* adh = adv + head * Ch + cb;
        #pragma unroll
        for (int ma = 0; ma < 2; ma++) {
            float pe0 = 0.f, pd0 = 0.f, pe1 = 0.f, pd1 = 0.f;
            #pragma unroll
            for (int na = 0; na < 4; na++) {
                int cl = wn * 32 + na * 8 + t * 2;
                float w0 = avh[cl], w1 = avh[cl + 1];
                float d0 = adh[cl], d1 = adh[cl + 1];
                pe0 += acc[ma][na][0] * w0 + acc[ma][na][1] * w1;
                pd0 += acc[ma][na][0] * d0 + acc[ma][na][1] * d1;
                pe1 += acc[ma][na][2] * w0 + acc[ma][na][3] * w1;
                pd1 += acc[ma][na][2] * d0 + acc[ma][na][3] * d1;
            }
            #pragma unroll
            for (int o = 1; o <= 2; o <<= 1) {
                pe0 += __shfl_xor_sync(0xffffffff, pe0, o);
                pd0 += __shfl_xor_sync(0xffffffff, pd0, o);
                pe1 += __shfl_xor_sync(0xffffffff, pe1, o);
                pd1 += __shfl_xor_sync(0xffffffff, pd1, o);
            }
            if (t == 0) {
                int r = rowBase + wm * 32 + ma * 16 + g;
                if (r < M) {
                    atomicAdd(&esOut[(size_t)r * H + head], pe0);
                    atomicAdd(&edOut[(size_t)r * H + head], pd0);
                }
                if (r + 8 < M) {
                    atomicAdd(&esOut[(size_t)(r + 8) * H + head], pe1);
                    atomicAdd(&edOut[(size_t)(r + 8) * H + head], pd1);
                }
            }
        }
    }
}

// ================= graph kernels =============================================
__global__ void edge_w(int ET, int H) {
    int tdx = blockIdx.x * blockDim.x + threadIdx.x;
    if (tdx >= ET * H) return;
    int eid = tdx / H, hh = tdx - eid * H;
    float e = g_es[(size_t)g_src[eid] * H + hh] + g_ed[(size_t)g_dst[eid] * H + hh];
    e = e > 0.f ? e : 0.2f * e;
    g_w[tdx] = expf(e);
}

// CSR aggregate + bias + ELU + bf16 split (layers 1-2, C == 128)
__global__ void agg_split(const float* __restrict__ h, const float* __restrict__ b,
                          __nv_bfloat16* __restrict__ hi, __nv_bfloat16* __restrict__ lo,
                          int N, int H) {
    int wid = (blockIdx.x * blockDim.x + threadIdx.x) >> 5;
    int lane = threadIdx.x & 31;
    if (wid >= N * H) return;
    int d = wid / H, hh = wid - d * H;
    int e0 = g_roff[d], e1 = g_roff[d + 1];

    float4 acc = make_float4(0.f, 0.f, 0.f, 0.f);
    float z = 0.f;

    for (int base = e0; base < e1; base += 32) {
        int e = base + lane;
        int sv = 0; float wv = 0.f;
        if (e < e1) {
            int id = g_eid[e];
            sv = g_src[id];
            wv = g_w[(size_t)id * H + hh];
        }
        z += wv;
        int m = min(32, e1 - base);
        for (int j = 0; j < m; j++) {
            int s = __shfl_sync(0xffffffff, sv, j);
            float wj = __shfl_sync(0xffffffff, wv, j);
            const float4* hp = (const float4*)(h + (size_t)s * H * 128 + (size_t)hh * 128);
            float4 v = hp[lane];
            acc.x += wj * v.x; acc.y += wj * v.y;
            acc.z += wj * v.z; acc.w += wj * v.w;
        }
    }
    #pragma unroll
    for (int o = 16; o; o >>= 1) z += __shfl_xor_sync(0xffffffff, z, o);
    float invz = 1.f / (z + 1e-16f);

    const float4 bv = *(const float4*)(b + hh * 128 + lane * 4);
    float v0 = acc.x * invz + bv.x;  v0 = v0 > 0.f ? v0 : expm1f(v0);
    float v1 = acc.y * invz + bv.y;  v1 = v1 > 0.f ? v1 : expm1f(v1);
    float v2 = acc.z * invz + bv.z;  v2 = v2 > 0.f ? v2 : expm1f(v2);
    float v3 = acc.w * invz + bv.w;  v3 = v3 > 0.f ? v3 : expm1f(v3);

    __nv_bfloat162 h01, h23, l01, l23;
    h01.x = __float2bfloat16(v0); h01.y = __float2bfloat16(v1);
    h23.x = __float2bfloat16(v2); h23.y = __float2bfloat16(v3);
    l01.x = __float2bfloat16(v0 - __bfloat162float(h01.x));
    l01.y = __float2bfloat16(v1 - __bfloat162float(h01.y));
    l23.x = __float2bfloat16(v2 - __bfloat162float(h23.x));
    l23.y = __float2bfloat16(v3 - __bfloat162float(h23.y));

    size_t obase = (size_t)d * H * 128 + (size_t)hh * 128 + lane * 4;
    *(uint2*)(hi + obase) = make_uint2(*(uint32_t*)&h01, *(uint32_t*)&h23);
    *(uint2*)(lo + obase) = make_uint2(*(uint32_t*)&l01, *(uint32_t*)&l23);
}

// CSR aggregate + bias + ELU + risk head (layer 3, H=1, C=64) -> d_out
__global__ void agg_risk(const float* __restrict__ h, const float* __restrict__ b,
                         const float* __restrict__ Wr, const float* __restrict__ br,
                         float* __restrict__ out, int N) {
    int wid = (blockIdx.x * blockDim.x + threadIdx.x) >> 5;
    int lane = threadIdx.x & 31;
    if (wid >= N) return;
    int d = wid;
    int e0 = g_roff[d], e1 = g_roff[d + 1];

    float a0 = 0.f, a1 = 0.f, z = 0.f;
    for (int base = e0; base < e1; base += 32) {
        int e = base + lane;
        int sv = 0; float wv = 0.f;
        if (e < e1) {
            int id = g_eid[e];
            sv = g_src[id];
            wv = g_w[id];
        }
        z += wv;
        int m = min(32, e1 - base);
        for (int j = 0; j < m; j++) {
            int s = __shfl_sync(0xffffffff, sv, j);
            float wj = __shfl_sync(0xffffffff, wv, j);
            const float2* hp = (const float2*)(h + (size_t)s * 64);
            float2 v = hp[lane];
            a0 += wj * v.x; a1 += wj * v.y;
        }
    }
    #pragma unroll
    for (int o = 16; o; o >>= 1) z += __shfl_xor_sync(0xffffffff, z, o);
    float invz = 1.f / (z + 1e-16f);

    float v0 = a0 * invz + b[lane * 2];      v0 = v0 > 0.f ? v0 : expm1f(v0);
    float v1 = a1 * invz + b[lane * 2 + 1];  v1 = v1 > 0.f ? v1 : expm1f(v1);
    float s = v0 * Wr[lane * 2] + v1 * Wr[lane * 2 + 1];
    #pragma unroll
    for (int o = 16; o; o >>= 1) s += __shfl_xor_sync(0xffffffff, s, o);
    if (lane == 0) out[d] = 1.f / (1.f + expf(-(s + br[0])));
}

// ================= launch ====================================================
extern "C" void kernel_launch(void* const* d_in, const int* in_sizes, int n_in,
                              void* d_out, int out_size) {
    const float* x   = (const float*)d_in[0];
    const void*  ei  = d_in[1];
    const float* W1  = (const float*)d_in[2];
    const float* as1 = (const float*)d_in[3];
    const float* ad1 = (const float*)d_in[4];
    const float* b1  = (const float*)d_in[5];
    const float* W2  = (const float*)d_in[6];
    const float* as2 = (const float*)d_in[7];
    const float* ad2 = (const float*)d_in[8];
    const float* b2  = (const float*)d_in[9];
    const float* W3  = (const float*)d_in[10];
    const float* as3 = (const float*)d_in[11];
    const float* ad3 = (const float*)d_in[12];
    const float* b3  = (const float*)d_in[13];
    const float* Wr  = (const float*)d_in[14];
    const float* br  = (const float*)d_in[15];

    const int N  = in_sizes[0] / 66;
    const int E  = in_sizes[1] / 2;
    const int ET = E + N;
    const int nb = (N + SCAN_B - 1) / SCAN_B;

    cudaFuncSetAttribute(gemm_mma, cudaFuncAttributeMaxDynamicSharedMemorySize, SMEM_GEMM);

    void *p_h, *p_es, *p_ed, *p_wh, *p_wl, *p_ah, *p_al, *p_cnt;
    cudaGetSymbolAddress(&p_h,  g_h1);
    cudaGetSymbolAddress(&p_es, g_es);
    cudaGetSymbolAddress(&p_ed, g_ed);
    cudaGetSymbolAddress(&p_wh, g_wth);
    cudaGetSymbolAddress(&p_wl, g_wtl);
    cudaGetSymbolAddress(&p_ah, g_ah);
    cudaGetSymbolAddress(&p_al, g_al);
    cudaGetSymbolAddress(&p_cnt, g_cnt);

    float* h  = (float*)p_h;
    float* es = (float*)p_es; float* ed = (float*)p_ed;
    __nv_bfloat16* wh = (__nv_bfloat16*)p_wh;
    __nv_bfloat16* wl = (__nv_bfloat16*)p_wl;
    __nv_bfloat16* ah = (__nv_bfloat16*)p_ah;
    __nv_bfloat16* al = (__nv_bfloat16*)p_al;

    const int rowTiles = (N + 127) / 128;

    // ---- edges + CSR (built once) ----
    detect_dtype<<<1, 32>>>(ei, N);
    prep_edges<<<(ET + 255) / 256, 256>>>(ei, E, ET);
    cudaMemsetAsync(p_cnt, 0, N * sizeof(int));
    csr_hist<<<(ET + 255) / 256, 256>>>(ET);
    scan1<<<nb, SCAN_B>>>(N);
    scan2<<<1, 64>>>(nb);
    scan3<<<nb, SCAN_B>>>(N, ET);
    csr_fill<<<(ET + 255) / 256, 256>>>(ET);

    // ---------------- layer 1: 66 -> 8x128 (Nc=1024, Kpad=128, H=8, C=128) --
    cudaMemsetAsync(p_es, 0, (size_t)N * 8 * sizeof(float));
    cudaMemsetAsync(p_ed, 0, (size_t)N * 8 * sizeof(float));
    split_x<<<((N * 128) + 255) / 256, 256>>>(x, ah, al, N, 66, 128);
    prep_w<<<(1024 * 128 + 255) / 256, 256>>>(W1, wh, wl, 66, 1024, 128);
    {
        dim3 g(1024 / 64, rowTiles);
        gemm_mma<<<g, 256, SMEM_GEMM>>>(ah, al, wh, wl, h, N, 128, 1024,
                                        as1, ad1, es, ed, 8, 128);
    }
    edge_w<<<(ET * 8 + 255) / 256, 256>>>(ET, 8);
    agg_split<<<(N * 8 + 7) / 8, 256>>>(h, b1, ah, al, N, 8);

    // ---------------- layer 2: 1024 -> 128 (Nc=128, Kpad=1024, H=1, C=128) ---
    cudaMemsetAsync(p_es, 0, (size_t)N * sizeof(float));
    cudaMemsetAsync(p_ed, 0, (size_t)N * sizeof(float));
    prep_w<<<(128 * 1024 + 255) / 256, 256>>>(W2, wh, wl, 1024, 128, 1024);
    {
        dim3 g(128 / 64, rowTiles);
        gemm_mma<<<g, 256, SMEM_GEMM>>>(ah, al, wh, wl, h, N, 1024, 128,
                                        as2, ad2, es, ed, 1, 128);
    }
    edge_w<<<(ET + 255) / 256, 256>>>(ET, 1);
    agg_split<<<(N + 7) / 8, 256>>>(h, b2, ah, al, N, 1);

    // ---------------- layer 3: 128 -> 64 (Nc=64, Kpad=128, H=1, C=64) --------
    cudaMemsetAsync(p_es, 0, (size_t)N * sizeof(float));
    cudaMemsetAsync(p_ed, 0, (size_t)N * sizeof(float));
    prep_w<<<(64 * 128 + 255) / 256, 256>>>(W3, wh, wl, 128, 64, 128);
    {
        dim3 g(1, rowTiles);
        gemm_mma<<<g, 256, SMEM_GEMM>>>(ah, al, wh, wl, h, N, 128, 64,
                                        as3, ad3, es, ed, 1, 64);
    }
    edge_w<<<(ET + 255) / 256, 256>>>(ET, 1);
    agg_risk<<<(N + 7) / 8, 256>>>(h, b3, Wr, br, (float*)d_out, N);
}

// round 16
// speedup vs baseline: 1.4315x; 1.0230x over previous
#include <cuda_runtime.h>
#include <cuda_bf16.h>
#include <math.h>
#include <stdint.h>

#define NMAX 50000
#define EMAX 200000
#define ETMAX (NMAX + EMAX)

// ---------------- scratch (device globals; no allocations allowed) ----------
__device__ float g_h1[(size_t)NMAX * 1024];   // GEMM outputs (h), reused per layer
__device__ float g_es[(size_t)NMAX * 8];
__device__ float g_ed[(size_t)NMAX * 8];
__device__ int   g_src[ETMAX];
__device__ int   g_dst[ETMAX];
__device__ int   g_is64;
// CSR by dst
__device__ int   g_cnt[NMAX];
__device__ int   g_roff[NMAX + 1];
__device__ int   g_pos[NMAX];
__device__ int   g_bsum[64];
__device__ int   g_eid[ETMAX];
// pre-split A operand (hi/lo bf16), [N][Kpad]
__device__ __nv_bfloat16 g_ah[(size_t)NMAX * 1024];
__device__ __nv_bfloat16 g_al[(size_t)NMAX * 1024];
// transposed + hi/lo-split weights, [Nc][Kpad] bf16
__device__ __nv_bfloat16 g_wth[131072];
__device__ __nv_bfloat16 g_wtl[131072];

// ================= edge preprocessing =======================================
__global__ void detect_dtype(const void* ei, int N) {
    if (blockIdx.x == 0 && threadIdx.x == 0) {
        const long long* p = (const long long*)ei;
        int ok = 1;
        for (int i = 0; i < 64; i++) {
            long long v = p[i];
            if (v < 0 || v >= (long long)N) { ok = 0; break; }
        }
        g_is64 = ok;
    }
}
__global__ void prep_edges(const void* ei, int E, int ET) {
    int i = blockIdx.x * blockDim.x + threadIdx.x;
    if (i >= ET) return;
    int s, d;
    if (i < E) {
        if (g_is64) { const long long* p = (const long long*)ei; s = (int)p[i]; d = (int)p[E + i]; }
        else        { const int* p = (const int*)ei; s = p[i]; d = p[E + i]; }
    } else { s = d = i - E; }
    g_src[i] = s; g_dst[i] = d;
}

// ---------------- CSR build --------------------------------------------------
__global__ void csr_hist(int ET) {
    int i = blockIdx.x * blockDim.x + threadIdx.x;
    if (i < ET) atomicAdd(&g_cnt[g_dst[i]], 1);
}
#define SCAN_B 1024
__global__ void scan1(int n) {
    __shared__ int sh[SCAN_B];
    int gid = blockIdx.x * SCAN_B + threadIdx.x;
    int v = (gid < n) ? g_cnt[gid] : 0;
    sh[threadIdx.x] = v;
    __syncthreads();
    for (int o = 1; o < SCAN_B; o <<= 1) {
        int t = (threadIdx.x >= o) ? sh[threadIdx.x - o] : 0;
        __syncthreads();
        sh[threadIdx.x] += t;
        __syncthreads();
    }
    if (gid < n) g_roff[gid] = sh[threadIdx.x] - v;   // exclusive
    if (threadIdx.x == SCAN_B - 1) g_bsum[blockIdx.x] = sh[threadIdx.x];
}
__global__ void scan2(int nb) {
    __shared__ int sh[64];
    int v = (threadIdx.x < nb) ? g_bsum[threadIdx.x] : 0;
    sh[threadIdx.x] = v;
    __syncthreads();
    for (int o = 1; o < 64; o <<= 1) {
        int t = (threadIdx.x >= o) ? sh[threadIdx.x - o] : 0;
        __syncthreads();
        sh[threadIdx.x] += t;
        __syncthreads();
    }
    if (threadIdx.x < nb) g_bsum[threadIdx.x] = sh[threadIdx.x] - v;
}
__global__ void scan3(int n, int ET) {
    int gid = blockIdx.x * SCAN_B + threadIdx.x;
    if (gid < n) {
        int v = g_roff[gid] + g_bsum[blockIdx.x];
        g_roff[gid] = v;
        g_pos[gid] = v;
    }
    if (gid == 0) g_roff[n] = ET;
}
__global__ void csr_fill(int ET) {
    int i = blockIdx.x * blockDim.x + threadIdx.x;
    if (i >= ET) return;
    int slot = atomicAdd(&g_pos[g_dst[i]], 1);
    g_eid[slot] = i;
}

// ---------------- weight / input prep ---------------------------------------
__global__ void prep_w(const float* __restrict__ W, __nv_bfloat16* __restrict__ hi,
                       __nv_bfloat16* __restrict__ lo, int K, int N, int Kpad) {
    int idx = blockIdx.x * blockDim.x + threadIdx.x;
    if (idx >= N * Kpad) return;
    int n = idx / Kpad, k = idx - n * Kpad;
    float v = (k < K) ? W[(size_t)k * N + n] : 0.f;
    __nv_bfloat16 h = __float2bfloat16(v);
    hi[idx] = h;
    lo[idx] = __float2bfloat16(v - __bfloat162float(h));
}
__global__ void split_x(const float* __restrict__ x, __nv_bfloat16* __restrict__ hi,
                        __nv_bfloat16* __restrict__ lo, int N, int K, int Kpad) {
    int idx = blockIdx.x * blockDim.x + threadIdx.x;
    if (idx >= N * Kpad) return;
    int n = idx / Kpad, k = idx - n * Kpad;
    float v = (k < K) ? x[(size_t)n * K + k] : 0.f;
    __nv_bfloat16 h = __float2bfloat16(v);
    hi[idx] = h;
    lo[idx] = __float2bfloat16(v - __bfloat162float(h));
}

// ================= mma.sync bf16-split GEMM (ldmatrix + 2-stage cp.async) ====
#define APAD 72
#define A_ELEMS (128 * APAD)
#define B_ELEMS (64 * APAD)
#define STAGE_ELEMS (2 * A_ELEMS + 2 * B_ELEMS)      // 27648 elems = 55296 B
#define SMEM_GEMM (2 * STAGE_ELEMS * 2)              // 110592 bytes

__device__ __forceinline__ void mma_bf16(float* c, uint32_t a0, uint32_t a1,
                                         uint32_t a2, uint32_t a3,
                                         uint32_t b0, uint32_t b1) {
    asm volatile(
        "mma.sync.aligned.m16n8k16.row.col.f32.bf16.bf16.f32 "
        "{%0,%1,%2,%3}, {%4,%5,%6,%7}, {%8,%9}, {%0,%1,%2,%3};"
        : "+f"(c[0]), "+f"(c[1]), "+f"(c[2]), "+f"(c[3])
        : "r"(a0), "r"(a1), "r"(a2), "r"(a3), "r"(b0), "r"(b1));
}
__device__ __forceinline__ void ldmx4(uint32_t* r, uint32_t saddr) {
    asm volatile("ldmatrix.sync.aligned.m8n8.x4.shared.b16 {%0,%1,%2,%3}, [%4];"
                 : "=r"(r[0]), "=r"(r[1]), "=r"(r[2]), "=r"(r[3]) : "r"(saddr));
}
__device__ __forceinline__ void cp16(uint32_t saddr, const void* g, int src_sz) {
    asm volatile("cp.async.cg.shared.global [%0], [%1], 16, %2;"
                 :: "r"(saddr), "l"(g), "r"(src_sz) : "memory");
}

__global__ void __launch_bounds__(256, 2)
gemm_mma(const __nv_bfloat16* __restrict__ Ah, const __nv_bfloat16* __restrict__ Al,
         const __nv_bfloat16* __restrict__ Bh, const __nv_bfloat16* __restrict__ Bl,
         float* __restrict__ C, int M, int Kpad, int Nc,
         const float* __restrict__ av, const float* __restrict__ adv,
         float* __restrict__ esOut, float* __restrict__ edOut, int H, int Ch) {
    extern __shared__ __nv_bfloat16 sm[];
    const uint32_t smb = (uint32_t)__cvta_generic_to_shared(sm);

    const int tid = threadIdx.x;
    const int rowBase = blockIdx.y * 128, colBase = blockIdx.x * 64;
    const int warp = tid >> 5, lane = tid & 31;
    const int wm = warp & 3, wn = warp >> 2;
    const int g = lane >> 2, t = lane & 3;
    const int lrow = lane & 7;

    // ldmatrix per-lane offsets (element units):
    const int aRowOff = lrow + ((lane >> 3) & 1) * 8;
    const int aColOff = (lane >> 4) * 8;
    const int bRowOff = lrow + (lane >> 4) * 8;
    const int bColOff = ((lane >> 3) & 1) * 8;

    float acc[2][4][4] = {};
    const int nCh = Kpad >> 6;

    // stage loader (12 cp16 per thread): identical coverage to the R15 loader
    auto load_stage = [&](int s, int k0) {
        const uint32_t sb = smb + (uint32_t)s * STAGE_ELEMS * 2;
        #pragma unroll
        for (int i = 0; i < 4; i++) {
            int lin = tid + (i << 8);
            int row = lin >> 3, u = lin & 7;
            int gr = rowBase + row;
            int ok = (gr < M) ? 16 : 0;
            int grc = (gr < M) ? gr : 0;
            size_t gidx = (size_t)grc * Kpad + k0 + (u << 3);
            uint32_t so = sb + (uint32_t)(row * APAD + (u << 3)) * 2;
            cp16(so, Ah + gidx, ok);
            cp16(so + (uint32_t)A_ELEMS * 2, Al + gidx, ok);
        }
        #pragma unroll
        for (int i = 0; i < 2; i++) {
            int lin = tid + (i << 8);
            int n = lin >> 3, u = lin & 7;
            size_t gidx = (size_t)(colBase + n) * Kpad + k0 + (u << 3);
            uint32_t so = sb + (uint32_t)(2 * A_ELEMS + n * APAD + (u << 3)) * 2;
            cp16(so, Bh + gidx, 16);
            cp16(so + (uint32_t)B_ELEMS * 2, Bl + gidx, 16);
        }
    };

    load_stage(0, 0);
    asm volatile("cp.async.commit_group;" ::: "memory");

    for (int c = 0; c < nCh; c++) {
        if (c + 1 < nCh) {
            load_stage((c + 1) & 1, (c + 1) << 6);
            asm volatile("cp.async.commit_group;" ::: "memory");
            asm volatile("cp.async.wait_group 1;" ::: "memory");
        } else {
            asm volatile("cp.async.wait_group 0;" ::: "memory");
        }
        __syncthreads();

        const uint32_t sb = smb + (uint32_t)(c & 1) * STAGE_ELEMS * 2;
        const uint32_t sAh32 = sb;
        const uint32_t sAl32 = sb + (uint32_t)A_ELEMS * 2;
        const uint32_t sBh32 = sb + (uint32_t)(2 * A_ELEMS) * 2;
        const uint32_t sBl32 = sBh32 + (uint32_t)B_ELEMS * 2;

        #pragma unroll
        for (int ks = 0; ks < 4; ks++) {
            const int kbase = ks * 16;
            uint32_t ah[2][4], al[2][4];
            #pragma unroll
            for (int ma = 0; ma < 2; ma++) {
                uint32_t off = (uint32_t)(((wm * 32 + ma * 16 + aRowOff) * APAD
                                           + kbase + aColOff) * 2);
                ldmx4(ah[ma], sAh32 + off);
                ldmx4(al[ma], sAl32 + off);
            }
            uint32_t bh[2][4], bl[2][4];
            #pragma unroll
            for (int p = 0; p < 2; p++) {
                uint32_t off = (uint32_t)(((wn * 32 + p * 16 + bRowOff) * APAD
                                           + kbase + bColOff) * 2);
                ldmx4(bh[p], sBh32 + off);
                ldmx4(bl[p], sBl32 + off);
            }
            #pragma unroll
            for (int na = 0; na < 4; na++) {
                const int p = na >> 1, q = (na & 1) << 1;
                uint32_t bh0 = bh[p][q], bh1 = bh[p][q + 1];
                uint32_t bl0 = bl[p][q], bl1 = bl[p][q + 1];
                #pragma unroll
                for (int ma = 0; ma < 2; ma++) {
                    mma_bf16(acc[ma][na], ah[ma][0], ah[ma][1], ah[ma][2], ah[ma][3], bh0, bh1);
                    mma_bf16(acc[ma][na], ah[ma][0], ah[ma][1], ah[ma][2], ah[ma][3], bl0, bl1);
                    mma_bf16(acc[ma][na], al[ma][0], al[ma][1], al[ma][2], al[ma][3], bh0, bh1);
                }
            }
        }
        __syncthreads();
    }

    #pragma unroll
    for (int ma = 0; ma < 2; ma++) {
        int row = rowBase + wm * 32 + ma * 16 + g;
        #pragma unroll
        for (int na = 0; na < 4; na++) {
            int col = colBase + wn * 32 + na * 8 + t * 2;
            if (row < M)
                *(float2*)(C + (size_t)row * Nc + col) = make_float2(acc[ma][na][0], acc[ma][na][1]);
            if (row + 8 < M)
                *(float2*)(C + (size_t)(row + 8) * Nc + col) = make_float2(acc[ma][na][2], acc[ma][na][3]);
        }
    }

    // ---- fused attention dots (tile cols lie in ONE head) ----
    {
        const int head = colBase / Ch;
        const int cb = colBase - head * Ch;
        const float* avh = av + head * Ch + cb;
        const float* adh = adv + head * Ch + cb;
        #pragma unroll
        for (int ma = 0; ma < 2; ma++) {
            float pe0 = 0.f, pd0 = 0.f, pe1 = 0.f, pd1 = 0.f;
            #pragma unroll
            for (int na = 0; na < 4; na++) {
                int cl = wn * 32 + na * 8 + t * 2;
                float w0 = avh[cl], w1 = avh[cl + 1];
                float d0 = adh[cl], d1 = adh[cl + 1];
                pe0 += acc[ma][na][0] * w0 + acc[ma][na][1] * w1;
                pd0 += acc[ma][na][0] * d0 + acc[ma][na][1] * d1;
                pe1 += acc[ma][na][2] * w0 + acc[ma][na][3] * w1;
                pd1 += acc[ma][na][2] * d0 + acc[ma][na][3] * d1;
            }
            #pragma unroll
            for (int o = 1; o <= 2; o <<= 1) {
                pe0 += __shfl_xor_sync(0xffffffff, pe0, o);
                pd0 += __shfl_xor_sync(0xffffffff, pd0, o);
                pe1 += __shfl_xor_sync(0xffffffff, pe1, o);
                pd1 += __shfl_xor_sync(0xffffffff, pd1, o);
            }
            if (t == 0) {
                int r = rowBase + wm * 32 + ma * 16 + g;
                if (r < M) {
                    atomicAdd(&esOut[(size_t)r * H + head], pe0);
                    atomicAdd(&edOut[(size_t)r * H + head], pd0);
                }
                if (r + 8 < M) {
                    atomicAdd(&esOut[(size_t)(r + 8) * H + head], pe1);
                    atomicAdd(&edOut[(size_t)(r + 8) * H + head], pd1);
                }
            }
        }
    }
}

// ================= fused graph aggregates ====================================
// CSR aggregate with INLINE edge weights + bias + ELU + bf16 split (C == 128)
__global__ void agg_split(const float* __restrict__ h, const float* __restrict__ es,
                          const float* __restrict__ ed, const float* __restrict__ b,
                          __nv_bfloat16* __restrict__ hi, __nv_bfloat16* __restrict__ lo,
                          int N, int H) {
    int wid = (blockIdx.x * blockDim.x + threadIdx.x) >> 5;
    int lane = threadIdx.x & 31;
    if (wid >= N * H) return;
    int d = wid / H, hh = wid - d * H;
    int e0 = g_roff[d], e1 = g_roff[d + 1];
    const float edv = ed[(size_t)d * H + hh];

    float4 acc = make_float4(0.f, 0.f, 0.f, 0.f);
    float z = 0.f;

    for (int base = e0; base < e1; base += 32) {
        int e = base + lane;
        int sv = 0; float wv = 0.f;
        if (e < e1) {
            int id = g_eid[e];
            sv = g_src[id];
            float ev = es[(size_t)sv * H + hh] + edv;
            ev = ev > 0.f ? ev : 0.2f * ev;
            wv = expf(ev);
        }
        z += wv;
        int m = min(32, e1 - base);
        for (int j = 0; j < m; j++) {
            int s = __shfl_sync(0xffffffff, sv, j);
            float wj = __shfl_sync(0xffffffff, wv, j);
            const float4* hp = (const float4*)(h + (size_t)s * H * 128 + (size_t)hh * 128);
            float4 v = hp[lane];
            acc.x += wj * v.x; acc.y += wj * v.y;
            acc.z += wj * v.z; acc.w += wj * v.w;
        }
    }
    #pragma unroll
    for (int o = 16; o; o >>= 1) z += __shfl_xor_sync(0xffffffff, z, o);
    float invz = 1.f / (z + 1e-16f);

    const float4 bv = *(const float4*)(b + hh * 128 + lane * 4);
    float v0 = acc.x * invz + bv.x;  v0 = v0 > 0.f ? v0 : expm1f(v0);
    float v1 = acc.y * invz + bv.y;  v1 = v1 > 0.f ? v1 : expm1f(v1);
    float v2 = acc.z * invz + bv.z;  v2 = v2 > 0.f ? v2 : expm1f(v2);
    float v3 = acc.w * invz + bv.w;  v3 = v3 > 0.f ? v3 : expm1f(v3);

    __nv_bfloat162 h01, h23, l01, l23;
    h01.x = __float2bfloat16(v0); h01.y = __float2bfloat16(v1);
    h23.x = __float2bfloat16(v2); h23.y = __float2bfloat16(v3);
    l01.x = __float2bfloat16(v0 - __bfloat162float(h01.x));
    l01.y = __float2bfloat16(v1 - __bfloat162float(h01.y));
    l23.x = __float2bfloat16(v2 - __bfloat162float(h23.x));
    l23.y = __float2bfloat16(v3 - __bfloat162float(h23.y));

    size_t obase = (size_t)d * H * 128 + (size_t)hh * 128 + lane * 4;
    *(uint2*)(hi + obase) = make_uint2(*(uint32_t*)&h01, *(uint32_t*)&h23);
    *(uint2*)(lo + obase) = make_uint2(*(uint32_t*)&l01, *(uint32_t*)&l23);
}

// CSR aggregate (inline w) + bias + ELU + risk head (H=1, C=64) -> d_out
__global__ void agg_risk(const float* __restrict__ h, const float* __restrict__ es,
                         const float* __restrict__ ed, const float* __restrict__ b,
                         const float* __restrict__ Wr, const float* __restrict__ br,
                         float* __restrict__ out, int N) {
    int wid = (blockIdx.x * blockDim.x + threadIdx.x) >> 5;
    int lane = threadIdx.x & 31;
    if (wid >= N) return;
    int d = wid;
    int e0 = g_roff[d], e1 = g_roff[d + 1];
    const float edv = ed[d];

    float a0 = 0.f, a1 = 0.f, z = 0.f;
    for (int base = e0; base < e1; base += 32) {
        int e = base + lane;
        int sv = 0; float wv = 0.f;
        if (e < e1) {
            int id = g_eid[e];
            sv = g_src[id];
            float ev = es[sv] + edv;
            ev = ev > 0.f ? ev : 0.2f * ev;
            wv = expf(ev);
        }
        z += wv;
        int m = min(32, e1 - base);
        for (int j = 0; j < m; j++) {
            int s = __shfl_sync(0xffffffff, sv, j);
            float wj = __shfl_sync(0xffffffff, wv, j);
            const float2* hp = (const float2*)(h + (size_t)s * 64);
            float2 v = hp[lane];
            a0 += wj * v.x; a1 += wj * v.y;
        }
    }
    #pragma unroll
    for (int o = 16; o; o >>= 1) z += __shfl_xor_sync(0xffffffff, z, o);
    float invz = 1.f / (z + 1e-16f);

    float v0 = a0 * invz + b[lane * 2];      v0 = v0 > 0.f ? v0 : expm1f(v0);
    float v1 = a1 * invz + b[lane * 2 + 1];  v1 = v1 > 0.f ? v1 : expm1f(v1);
    float s = v0 * Wr[lane * 2] + v1 * Wr[lane * 2 + 1];
    #pragma unroll
    for (int o = 16; o; o >>= 1) s += __shfl_xor_sync(0xffffffff, s, o);
    if (lane == 0) out[d] = 1.f / (1.f + expf(-(s + br[0])));
}

// ================= launch ====================================================
extern "C" void kernel_launch(void* const* d_in, const int* in_sizes, int n_in,
                              void* d_out, int out_size) {
    const float* x   = (const float*)d_in[0];
    const void*  ei  = d_in[1];
    const float* W1  = (const float*)d_in[2];
    const float* as1 = (const float*)d_in[3];
    const float* ad1 = (const float*)d_in[4];
    const float* b1  = (const float*)d_in[5];
    const float* W2  = (const float*)d_in[6];
    const float* as2 = (const float*)d_in[7];
    const float* ad2 = (const float*)d_in[8];
    const float* b2  = (const float*)d_in[9];
    const float* W3  = (const float*)d_in[10];
    const float* as3 = (const float*)d_in[11];
    const float* ad3 = (const float*)d_in[12];
    const float* b3  = (const float*)d_in[13];
    const float* Wr  = (const float*)d_in[14];
    const float* br  = (const float*)d_in[15];

    const int N  = in_sizes[0] / 66;
    const int E  = in_sizes[1] / 2;
    const int ET = E + N;
    const int nb = (N + SCAN_B - 1) / SCAN_B;

    cudaFuncSetAttribute(gemm_mma, cudaFuncAttributeMaxDynamicSharedMemorySize, SMEM_GEMM);

    void *p_h, *p_es, *p_ed, *p_wh, *p_wl, *p_ah, *p_al, *p_cnt;
    cudaGetSymbolAddress(&p_h,  g_h1);
    cudaGetSymbolAddress(&p_es, g_es);
    cudaGetSymbolAddress(&p_ed, g_ed);
    cudaGetSymbolAddress(&p_wh, g_wth);
    cudaGetSymbolAddress(&p_wl, g_wtl);
    cudaGetSymbolAddress(&p_ah, g_ah);
    cudaGetSymbolAddress(&p_al, g_al);
    cudaGetSymbolAddress(&p_cnt, g_cnt);

    float* h  = (float*)p_h;
    float* es = (float*)p_es; float* ed = (float*)p_ed;
    __nv_bfloat16* wh = (__nv_bfloat16*)p_wh;
    __nv_bfloat16* wl = (__nv_bfloat16*)p_wl;
    __nv_bfloat16* ah = (__nv_bfloat16*)p_ah;
    __nv_bfloat16* al = (__nv_bfloat16*)p_al;

    const int rowTiles = (N + 127) / 128;

    // ---- edges + CSR (built once) ----
    detect_dtype<<<1, 32>>>(ei, N);
    prep_edges<<<(ET + 255) / 256, 256>>>(ei, E, ET);
    cudaMemsetAsync(p_cnt, 0, N * sizeof(int));
    csr_hist<<<(ET + 255) / 256, 256>>>(ET);
    scan1<<<nb, SCAN_B>>>(N);
    scan2<<<1, 64>>>(nb);
    scan3<<<nb, SCAN_B>>>(N, ET);
    csr_fill<<<(ET + 255) / 256, 256>>>(ET);

    // ---------------- layer 1: 66 -> 8x128 (Nc=1024, Kpad=128, H=8, C=128) --
    cudaMemsetAsync(p_es, 0, (size_t)N * 8 * sizeof(float));
    cudaMemsetAsync(p_ed, 0, (size_t)N * 8 * sizeof(float));
    split_x<<<((N * 128) + 255) / 256, 256>>>(x, ah, al, N, 66, 128);
    prep_w<<<(1024 * 128 + 255) / 256, 256>>>(W1, wh, wl, 66, 1024, 128);
    {
        dim3 g(1024 / 64, rowTiles);
        gemm_mma<<<g, 256, SMEM_GEMM>>>(ah, al, wh, wl, h, N, 128, 1024,
                                        as1, ad1, es, ed, 8, 128);
    }
    agg_split<<<(N * 8 + 7) / 8, 256>>>(h, es, ed, b1, ah, al, N, 8);

    // ---------------- layer 2: 1024 -> 128 (Nc=128, Kpad=1024, H=1, C=128) ---
    cudaMemsetAsync(p_es, 0, (size_t)N * sizeof(float));
    cudaMemsetAsync(p_ed, 0, (size_t)N * sizeof(float));
    prep_w<<<(128 * 1024 + 255) / 256, 256>>>(W2, wh, wl, 1024, 128, 1024);
    {
        dim3 g(128 / 64, rowTiles);
        gemm_mma<<<g, 256, SMEM_GEMM>>>(ah, al, wh, wl, h, N, 1024, 128,
                                        as2, ad2, es, ed, 1, 128);
    }
    agg_split<<<(N + 7) / 8, 256>>>(h, es, ed, b2, ah, al, N, 1);

    // ---------------- layer 3: 128 -> 64 (Nc=64, Kpad=128, H=1, C=64) --------
    cudaMemsetAsync(p_es, 0, (size_t)N * sizeof(float));
    cudaMemsetAsync(p_ed, 0, (size_t)N * sizeof(float));
    prep_w<<<(64 * 128 + 255) / 256, 256>>>(W3, wh, wl, 128, 64, 128);
    {
        dim3 g(1, rowTiles);
        gemm_mma<<<g, 256, SMEM_GEMM>>>(ah, al, wh, wl, h, N, 128, 64,
                                        as3, ad3, es, ed, 1, 64);
    }
    agg_risk<<<(N + 7) / 8, 256>>>(h, es, ed, b3, Wr, br, (float*)d_out, N);
}